// round 7
// baseline (speedup 1.0000x reference)
#include <cuda_runtime.h>
#include <cuda_bf16.h>
#include <math.h>
#include <stdint.h>

#define S_LEN 2048
#define E_DIM 768
#define B_SZ  2
#define NH_R  6
#define NH_C  2
#define HD_R  128
#define HD_C  384
#define M_TOT 4096
#define NQKV  4608

// smem strides (uint2 units); stride mod 16 == 4 -> conflict-free LDS.64 frags
#define SP_A  20
#define SP_BN 68
#define SP_BT 20

// flash smem geometry (uint2 units)
#define FQ_S 68
#define FK_S 68
#define FV_S 132
#define FQ_SZ (128*FQ_S)
#define FK_SZ (64*FK_S)
#define FV_SZ (32*FV_S)
#define FLASH_SMEM ((FQ_SZ + 2*FK_SZ + 2*FV_SZ)*8 + 2*64*4)   // 207,360 B

// -------- scratch ------------------------------------------------------------
__device__ uint2 g_xp[(size_t)M_TOT*384];
__device__ uint2 g_wqkvp[(size_t)384*NQKV];
__device__ float g_bqkv[NQKV];
__device__ float g_qkv[(size_t)M_TOT*NQKV];
__device__ uint2 g_qkvp[(size_t)M_TOT*2304];
__device__ uint2 g_vf2[(size_t)B_SZ*1024*1536];
__device__ float g_sc[(size_t)B_SZ*NH_C*S_LEN*S_LEN];
__device__ uint2 g_scp[(size_t)B_SZ*NH_C*S_LEN*1024];
__device__ uint2 g_arp[(size_t)M_TOT*384];
__device__ uint2 g_acp[(size_t)M_TOT*384];
__device__ uint2 g_wop[(size_t)384*1536];
__device__ uint2 g_outwp[(size_t)768*768];
__device__ uint2 g_catp[(size_t)M_TOT*768];

// -------- helpers --------------------------------------------------------------
__device__ __forceinline__ uint32_t smem_u32(const void* p) {
    return (uint32_t)__cvta_generic_to_shared(p);
}
#define CP16(sa, ga) asm volatile("cp.async.cg.shared.global [%0], [%1], 16;" :: "r"(sa), "l"(ga))
#define CP_COMMIT()  asm volatile("cp.async.commit_group;" ::: "memory")
#define CP_WAIT0()   asm volatile("cp.async.wait_group 0;" ::: "memory")

__device__ __forceinline__ uint32_t bf2w(float a, float b) {
    __nv_bfloat162 t;
    t.x = __float2bfloat16(a); t.y = __float2bfloat16(b);
    return *reinterpret_cast<uint32_t*>(&t);
}
__device__ __forceinline__ uint2 packpair(float e, float o) {
    __nv_bfloat16 he = __float2bfloat16(e);
    __nv_bfloat16 ho = __float2bfloat16(o);
    float le = e - __bfloat162float(he);
    float lo = o - __bfloat162float(ho);
    uint2 r;
    __nv_bfloat162 th; th.x = he; th.y = ho;
    r.x = *reinterpret_cast<uint32_t*>(&th);
    r.y = bf2w(le, lo);
    return r;
}

__device__ __forceinline__ void mma_bf16(float* c, const uint32_t* a, const uint32_t* b) {
    asm volatile(
        "mma.sync.aligned.m16n8k16.row.col.f32.bf16.bf16.f32 "
        "{%0,%1,%2,%3}, {%4,%5,%6,%7}, {%8,%9}, {%0,%1,%2,%3};"
        : "+f"(c[0]), "+f"(c[1]), "+f"(c[2]), "+f"(c[3])
        : "r"(a[0]), "r"(a[1]), "r"(a[2]), "r"(a[3]), "r"(b[0]), "r"(b[1]));
}

// ============================================================================
// small packing kernels
// ============================================================================
__global__ void pack_f2(const float* __restrict__ src, uint2* __restrict__ dst,
                        int Nsrc, int dstN, int col_off, int total)
{
    int idx = blockIdx.x * 256 + threadIdx.x;
    if (idx >= total) return;
    int p = idx / Nsrc, n = idx % Nsrc;
    dst[(long long)p * dstN + col_off + n] =
        packpair(src[(long long)(2 * p) * Nsrc + n], src[(long long)(2 * p + 1) * Nsrc + n]);
}

__global__ void fold_bias(const float* b0, const float* b1, const float* b2,
                          const float* b3, const float* b4, const float* b5,
                          const float* rcb, const float* ccb, float* Bv)
{
    int idx = blockIdx.x * 256 + threadIdx.x;
    if (idx >= NQKV) return;
    int blk = idx / E_DIM, c = idx % E_DIM;
    const float* bs;
    switch (blk) {
        case 0: bs = b0; break; case 1: bs = b1; break; case 2: bs = b2; break;
        case 3: bs = b3; break; case 4: bs = b4; break; default: bs = b5; break;
    }
    float v = bs[c];
    if (blk == 0) v += rcb[c];
    if (blk == 3) v += ccb[c];
    Bv[idx] = v;
}

__global__ void split_f1(const float* __restrict__ src, uint2* __restrict__ dst, int totalPairs)
{
    int idx = blockIdx.x * 256 + threadIdx.x;
    if (idx >= totalPairs) return;
    float2 f = ((const float2*)src)[idx];
    dst[idx] = packpair(f.x, f.y);
}

__global__ void split_v(const float* __restrict__ qkv, uint2* __restrict__ v)
{
    int idx = blockIdx.x * 256 + threadIdx.x;
    const int total = B_SZ * 1024 * 1536;
    if (idx >= total) return;
    int b = idx / (1024 * 1536);
    int r = idx % (1024 * 1536);
    int p = r / 1536, n = r % 1536;
    int col = (n < 768) ? (1536 + n) : (3072 + n);
    long long row = (long long)(b * 2048 + 2 * p) * NQKV;
    v[idx] = packpair(qkv[row + col], qkv[row + NQKV + col]);
}

// ============================================================================
// NN GEMM, bf16x3 (unchanged)
// ============================================================================
__global__ void __launch_bounds__(128) gemm_bf3_nn(
    const uint2* __restrict__ A, const uint2* __restrict__ B,
    float* __restrict__ Cf, uint2* __restrict__ Cp,
    const float* __restrict__ bias,
    int K, int lda2, int ldbN, int ldc, int ldc2,
    long long sA2, long long sBb, long long sBh,
    long long sCpb, long long sCph, int nh)
{
    __shared__ uint2 As[128 * SP_A];
    __shared__ uint2 Bs[16 * SP_BN];
    const int tid = threadIdx.x;
    const int wid = tid >> 5, lane = tid & 31;
    const int gid = lane >> 2, tig = lane & 3;
    const int wm = wid >> 1, wn = wid & 1;
    const int z = blockIdx.z, b = z / nh, h = z % nh;
    const uint2* Ap = A + (long long)z * sA2;
    const uint2* Bp = B + (long long)b * sBb + (long long)h * sBh;
    const int row0 = blockIdx.y * 128, col0 = blockIdx.x * 64;

    uint4 pa[8], pbuf[4];
    #pragma unroll
    for (int it = 0; it < 8; it++) {
        int lin = it * 128 + tid; int m = lin >> 3, p4 = (lin & 7) << 1;
        pa[it] = *(const uint4*)(Ap + (long long)(row0 + m) * lda2 + p4);
    }
    #pragma unroll
    for (int it = 0; it < 4; it++) {
        int lin = it * 128 + tid; int p = lin >> 5, n2 = (lin & 31) << 1;
        pbuf[it] = *(const uint4*)(Bp + (long long)p * ldbN + col0 + n2);
    }

    float acc[4][4][4] = {};

    for (int k0 = 0; k0 < K; k0 += 32) {
        #pragma unroll
        for (int it = 0; it < 8; it++) {
            int lin = it * 128 + tid; int m = lin >> 3, p4 = (lin & 7) << 1;
            *(uint4*)&As[m * SP_A + p4] = pa[it];
        }
        #pragma unroll
        for (int it = 0; it < 4; it++) {
            int lin = it * 128 + tid; int p = lin >> 5, n2 = (lin & 31) << 1;
            *(uint4*)&Bs[p * SP_BN + n2] = pbuf[it];
        }
        __syncthreads();
        if (k0 + 32 < K) {
            int k02 = (k0 + 32) >> 1;
            #pragma unroll
            for (int it = 0; it < 8; it++) {
                int lin = it * 128 + tid; int m = lin >> 3, p4 = (lin & 7) << 1;
                pa[it] = *(const uint4*)(Ap + (long long)(row0 + m) * lda2 + k02 + p4);
            }
            #pragma unroll
            for (int it = 0; it < 4; it++) {
                int lin = it * 128 + tid; int p = lin >> 5, n2 = (lin & 31) << 1;
                pbuf[it] = *(const uint4*)(Bp + (long long)(k02 + p) * ldbN + col0 + n2);
            }
        }
        #pragma unroll
        for (int pb2 = 0; pb2 < 16; pb2 += 8) {
            uint32_t bh[4][2], bl[4][2];
            #pragma unroll
            for (int j = 0; j < 4; j++) {
                int n = wn * 32 + j * 8 + gid;
                uint2 e0 = Bs[(pb2 + tig) * SP_BN + n];
                uint2 e1 = Bs[(pb2 + tig + 4) * SP_BN + n];
                bh[j][0] = e0.x; bl[j][0] = e0.y;
                bh[j][1] = e1.x; bl[j][1] = e1.y;
            }
            #pragma unroll
            for (int i = 0; i < 4; i++) {
                int mb = wm * 64 + i * 16 + gid;
                uint2 a0 = As[mb * SP_A + pb2 + tig];
                uint2 a1 = As[(mb + 8) * SP_A + pb2 + tig];
                uint2 a2 = As[mb * SP_A + pb2 + tig + 4];
                uint2 a3 = As[(mb + 8) * SP_A + pb2 + tig + 4];
                uint32_t ah[4] = {a0.x, a1.x, a2.x, a3.x};
                uint32_t al[4] = {a0.y, a1.y, a2.y, a3.y};
                #pragma unroll
                for (int j = 0; j < 4; j++) {
                    mma_bf16(acc[i][j], ah, bh[j]);
                    mma_bf16(acc[i][j], al, bh[j]);
                    mma_bf16(acc[i][j], ah, bl[j]);
                }
            }
        }
        __syncthreads();
    }

    uint2* Cpb = Cp ? (Cp + (long long)b * sCpb + (long long)h * sCph) : nullptr;
    #pragma unroll
    for (int i = 0; i < 4; i++) {
        int r0 = row0 + wm * 64 + i * 16 + gid;
        #pragma unroll
        for (int j = 0; j < 4; j++) {
            int c = col0 + wn * 32 + j * 8 + tig * 2;
            float b0 = 0.f, b1 = 0.f;
            if (bias) { b0 = bias[c]; b1 = bias[c + 1]; }
            float v00 = acc[i][j][0] + b0, v01 = acc[i][j][1] + b1;
            float v10 = acc[i][j][2] + b0, v11 = acc[i][j][3] + b1;
            if (Cf) {
                float2 t0 = {v00, v01}, t1 = {v10, v11};
                *(float2*)(Cf + (long long)r0 * ldc + c) = t0;
                *(float2*)(Cf + (long long)(r0 + 8) * ldc + c) = t1;
            }
            if (Cpb) {
                Cpb[(long long)r0 * ldc2 + (c >> 1)] = packpair(v00, v01);
                Cpb[(long long)(r0 + 8) * ldc2 + (c >> 1)] = packpair(v10, v11);
            }
        }
    }
}

// ============================================================================
// NT scores GEMM (cultural branch only; unchanged)
// ============================================================================
__global__ void __launch_bounds__(128) gemm_bf3_nt_scores(
    const uint2* __restrict__ Qb, const uint2* __restrict__ Kb,
    float* __restrict__ Sc,
    const float* __restrict__ am, const float* __restrict__ cm,
    float scale, int hd, int nh, int lda2)
{
    __shared__ uint2 As[128 * SP_A];
    __shared__ uint2 Bs[64 * SP_BT];
    const int tid = threadIdx.x;
    const int wid = tid >> 5, lane = tid & 31;
    const int gid = lane >> 2, tig = lane & 3;
    const int wm = wid >> 1, wn = wid & 1;
    const int z = blockIdx.z, b = z / nh, h = z % nh;
    const int hp = hd >> 1;
    const uint2* Qp = Qb + (long long)b * S_LEN * lda2 + h * hp;
    const uint2* Kp = Kb + (long long)b * S_LEN * lda2 + h * hp;
    float* Cpt = Sc + (long long)z * S_LEN * S_LEN;
    const int row0 = blockIdx.y * 128, col0 = blockIdx.x * 64;

    uint4 pa[8], pbuf[4];
    #pragma unroll
    for (int it = 0; it < 8; it++) {
        int lin = it * 128 + tid; int m = lin >> 3, p4 = (lin & 7) << 1;
        pa[it] = *(const uint4*)(Qp + (long long)(row0 + m) * lda2 + p4);
    }
    #pragma unroll
    for (int it = 0; it < 4; it++) {
        int lin = it * 128 + tid; int n = lin >> 3, p4 = (lin & 7) << 1;
        pbuf[it] = *(const uint4*)(Kp + (long long)(col0 + n) * lda2 + p4);
    }

    float acc[4][4][4] = {};

    for (int k0 = 0; k0 < hd; k0 += 32) {
        #pragma unroll
        for (int it = 0; it < 8; it++) {
            int lin = it * 128 + tid; int m = lin >> 3, p4 = (lin & 7) << 1;
            *(uint4*)&As[m * SP_A + p4] = pa[it];
        }
        #pragma unroll
        for (int it = 0; it < 4; it++) {
            int lin = it * 128 + tid; int n = lin >> 3, p4 = (lin & 7) << 1;
            *(uint4*)&Bs[n * SP_BT + p4] = pbuf[it];
        }
        __syncthreads();
        if (k0 + 32 < hd) {
            int k02 = (k0 + 32) >> 1;
            #pragma unroll
            for (int it = 0; it < 8; it++) {
                int lin = it * 128 + tid; int m = lin >> 3, p4 = (lin & 7) << 1;
                pa[it] = *(const uint4*)(Qp + (long long)(row0 + m) * lda2 + k02 + p4);
            }
            #pragma unroll
            for (int it = 0; it < 4; it++) {
                int lin = it * 128 + tid; int n = lin >> 3, p4 = (lin & 7) << 1;
                pbuf[it] = *(const uint4*)(Kp + (long long)(col0 + n) * lda2 + k02 + p4);
            }
        }
        #pragma unroll
        for (int pb2 = 0; pb2 < 16; pb2 += 8) {
            uint32_t bh[4][2], bl[4][2];
            #pragma unroll
            for (int j = 0; j < 4; j++) {
                int n = wn * 32 + j * 8 + gid;
                uint2 e0 = Bs[n * SP_BT + pb2 + tig];
                uint2 e1 = Bs[n * SP_BT + pb2 + tig + 4];
                bh[j][0] = e0.x; bl[j][0] = e0.y;
                bh[j][1] = e1.x; bl[j][1] = e1.y;
            }
            #pragma unroll
            for (int i = 0; i < 4; i++) {
                int mb = wm * 64 + i * 16 + gid;
                uint2 a0 = As[mb * SP_A + pb2 + tig];
                uint2 a1 = As[(mb + 8) * SP_A + pb2 + tig];
                uint2 a2 = As[mb * SP_A + pb2 + tig + 4];
                uint2 a3 = As[(mb + 8) * SP_A + pb2 + tig + 4];
                uint32_t ah[4] = {a0.x, a1.x, a2.x, a3.x};
                uint32_t al[4] = {a0.y, a1.y, a2.y, a3.y};
                #pragma unroll
                for (int j = 0; j < 4; j++) {
                    mma_bf16(acc[i][j], ah, bh[j]);
                    mma_bf16(acc[i][j], al, bh[j]);
                    mma_bf16(acc[i][j], ah, bl[j]);
                }
            }
        }
        __syncthreads();
    }

    #pragma unroll
    for (int i = 0; i < 4; i++) {
        int t0 = row0 + wm * 64 + i * 16 + gid;
        #pragma unroll
        for (int j = 0; j < 4; j++) {
            int s = col0 + wn * 32 + j * 8 + tig * 2;
            float m0 = am[b * S_LEN + s], m1 = am[b * S_LEN + s + 1];
            float n0 = m0, n1 = m1;
            if (cm) {
                const float* cmr0 = cm + ((long long)b * S_LEN + t0) * S_LEN;
                const float* cmr1 = cmr0 + 8LL * S_LEN;
                m0 += cmr0[s]; m1 += cmr0[s + 1];
                n0 += cmr1[s]; n1 += cmr1[s + 1];
            }
            float2 v0 = { acc[i][j][0] * scale + m0, acc[i][j][1] * scale + m1 };
            float2 v1 = { acc[i][j][2] * scale + n0, acc[i][j][3] * scale + n1 };
            *(float2*)(Cpt + (long long)t0 * S_LEN + s) = v0;
            *(float2*)(Cpt + (long long)(t0 + 8) * S_LEN + s) = v1;
        }
    }
}

// ============================================================================
// Flash-fused regular branch v2: 4 warps, warp tile M=32 (2 m-frags).
// K/V fragment loads amortized over 2 m-frags -> crossbar-bytes ~0.55x.
// ============================================================================
__global__ void __launch_bounds__(128, 1) flash_reg(
    const uint2* __restrict__ qkvp, const uint2* __restrict__ vf2,
    const float* __restrict__ am, uint2* __restrict__ arp, float scale)
{
    extern __shared__ uint2 sm[];
    uint2* Qs = sm;                        // 128 x FQ_S
    uint2* Ks = Qs + FQ_SZ;                // 2 x 64 x FK_S
    uint2* Vs = Ks + 2 * FK_SZ;            // 2 x 32 x FV_S
    float* ams = (float*)(Vs + 2 * FV_SZ); // 2 x 64

    const int tid = threadIdx.x, wid = tid >> 5, lane = tid & 31;
    const int gid = lane >> 2, tig = lane & 3;
    const int qt = blockIdx.x;
    const int z = blockIdx.y, b = z / NH_R, h = z % NH_R;

    const long long qrow0 = (long long)b * S_LEN + qt * 128;
    const uint2* Qg = qkvp + qrow0 * 2304 + h * 64;
    const uint2* Kg = qkvp + (long long)b * S_LEN * 2304 + 384 + h * 64;
    const uint2* Vg = vf2 + (long long)b * 1024 * 1536 + h * 128;
    const float* amb = am + (long long)b * S_LEN;

    // ---- load Q ----
    #pragma unroll
    for (int it = 0; it < 32; it++) {
        int lin = it * 128 + tid;
        int r = lin >> 5, p2 = (lin & 31) << 1;
        CP16(smem_u32(&Qs[r * FQ_S + p2]), Qg + (long long)r * 2304 + p2);
    }
    // ---- load K0/V0/am0 ----
    #pragma unroll
    for (int it = 0; it < 16; it++) {
        int lin = it * 128 + tid;
        int r = lin >> 5, p2 = (lin & 31) << 1;
        CP16(smem_u32(&Ks[r * FK_S + p2]), Kg + (long long)r * 2304 + p2);
    }
    #pragma unroll
    for (int it = 0; it < 16; it++) {
        int lin = it * 128 + tid;
        int p = lin >> 6, n2 = (lin & 63) << 1;
        CP16(smem_u32(&Vs[p * FV_S + n2]), Vg + (long long)p * 1536 + n2);
    }
    if (tid < 16) CP16(smem_u32(&ams[tid * 4]), amb + tid * 4);
    CP_COMMIT();

    float oac[2][16][4] = {};
    float mst[4] = {-1e30f, -1e30f, -1e30f, -1e30f};
    float lst[4] = {0.f, 0.f, 0.f, 0.f};
    const int mrow = wid * 32;

    CP_WAIT0();
    __syncthreads();

    for (int kt = 0; kt < 32; kt++) {
        if (kt + 1 < 32) {
            int nb = (kt + 1) & 1;
            uint2* Kd = Ks + nb * FK_SZ;
            uint2* Vd = Vs + nb * FV_SZ;
            #pragma unroll
            for (int it = 0; it < 16; it++) {
                int lin = it * 128 + tid;
                int r = lin >> 5, p2 = (lin & 31) << 1;
                CP16(smem_u32(&Kd[r * FK_S + p2]),
                     Kg + (long long)((kt + 1) * 64 + r) * 2304 + p2);
            }
            #pragma unroll
            for (int it = 0; it < 16; it++) {
                int lin = it * 128 + tid;
                int p = lin >> 6, n2 = (lin & 63) << 1;
                CP16(smem_u32(&Vd[p * FV_S + n2]),
                     Vg + (long long)((kt + 1) * 32 + p) * 1536 + n2);
            }
            if (tid < 16)
                CP16(smem_u32(&ams[nb * 64 + tid * 4]), amb + (kt + 1) * 64 + tid * 4);
            CP_COMMIT();
        }

        const uint2* Kb = Ks + (kt & 1) * FK_SZ;
        const uint2* Vb = Vs + (kt & 1) * FV_SZ;
        const float* amc = ams + (kt & 1) * 64;

        // ---- S = Q @ K^T (bf16x3), 2 m-frags per warp ----
        float sac[2][8][4] = {};
        #pragma unroll
        for (int t = 0; t < 8; t++) {
            uint32_t ah[2][4], al[2][4];
            #pragma unroll
            for (int i = 0; i < 2; i++) {
                int mr = mrow + i * 16 + gid;
                uint2 a0 = Qs[mr * FQ_S + 8 * t + tig];
                uint2 a1 = Qs[(mr + 8) * FQ_S + 8 * t + tig];
                uint2 a2 = Qs[mr * FQ_S + 8 * t + tig + 4];
                uint2 a3 = Qs[(mr + 8) * FQ_S + 8 * t + tig + 4];
                ah[i][0] = a0.x; ah[i][1] = a1.x; ah[i][2] = a2.x; ah[i][3] = a3.x;
                al[i][0] = a0.y; al[i][1] = a1.y; al[i][2] = a2.y; al[i][3] = a3.y;
            }
            #pragma unroll
            for (int j = 0; j < 8; j++) {
                uint2 e0 = Kb[(8 * j + gid) * FK_S + 8 * t + tig];
                uint2 e1 = Kb[(8 * j + gid) * FK_S + 8 * t + tig + 4];
                uint32_t bh[2] = {e0.x, e1.x};
                uint32_t bl[2] = {e0.y, e1.y};
                #pragma unroll
                for (int i = 0; i < 2; i++) {
                    mma_bf16(sac[i][j], ah[i], bh);
                    mma_bf16(sac[i][j], al[i], bh);
                    mma_bf16(sac[i][j], ah[i], bl);
                }
            }
        }

        // ---- scale + mask + online softmax (4 row-states per thread) ----
        uint32_t ph[2][4][4], pl[2][4][4];
        #pragma unroll
        for (int i = 0; i < 2; i++) {
            float mx0 = -1e30f, mx1 = -1e30f;
            #pragma unroll
            for (int j = 0; j < 8; j++) {
                float a0 = amc[8 * j + 2 * tig], a1 = amc[8 * j + 2 * tig + 1];
                sac[i][j][0] = sac[i][j][0] * scale + a0;
                sac[i][j][1] = sac[i][j][1] * scale + a1;
                sac[i][j][2] = sac[i][j][2] * scale + a0;
                sac[i][j][3] = sac[i][j][3] * scale + a1;
                mx0 = fmaxf(mx0, fmaxf(sac[i][j][0], sac[i][j][1]));
                mx1 = fmaxf(mx1, fmaxf(sac[i][j][2], sac[i][j][3]));
            }
            mx0 = fmaxf(mx0, __shfl_xor_sync(0xffffffffu, mx0, 1));
            mx0 = fmaxf(mx0, __shfl_xor_sync(0xffffffffu, mx0, 2));
            mx1 = fmaxf(mx1, __shfl_xor_sync(0xffffffffu, mx1, 1));
            mx1 = fmaxf(mx1, __shfl_xor_sync(0xffffffffu, mx1, 2));
            float mn0 = fmaxf(mst[2 * i], mx0), mn1 = fmaxf(mst[2 * i + 1], mx1);
            float sc0 = __expf(mst[2 * i] - mn0), sc1 = __expf(mst[2 * i + 1] - mn1);
            float ps0 = 0.f, ps1 = 0.f;
            #pragma unroll
            for (int j = 0; j < 8; j++) {
                sac[i][j][0] = __expf(sac[i][j][0] - mn0);
                sac[i][j][1] = __expf(sac[i][j][1] - mn0);
                sac[i][j][2] = __expf(sac[i][j][2] - mn1);
                sac[i][j][3] = __expf(sac[i][j][3] - mn1);
                ps0 += sac[i][j][0] + sac[i][j][1];
                ps1 += sac[i][j][2] + sac[i][j][3];
            }
            ps0 += __shfl_xor_sync(0xffffffffu, ps0, 1);
            ps0 += __shfl_xor_sync(0xffffffffu, ps0, 2);
            ps1 += __shfl_xor_sync(0xffffffffu, ps1, 1);
            ps1 += __shfl_xor_sync(0xffffffffu, ps1, 2);
            lst[2 * i]     = lst[2 * i] * sc0 + ps0;
            lst[2 * i + 1] = lst[2 * i + 1] * sc1 + ps1;
            mst[2 * i] = mn0; mst[2 * i + 1] = mn1;

            // rescale O for this m-frag
            #pragma unroll
            for (int n = 0; n < 16; n++) {
                oac[i][n][0] *= sc0; oac[i][n][1] *= sc0;
                oac[i][n][2] *= sc1; oac[i][n][3] *= sc1;
            }

            // pack P A-fragments
            #pragma unroll
            for (int t = 0; t < 4; t++) {
                uint2 w0 = packpair(sac[i][2 * t][0], sac[i][2 * t][1]);
                uint2 w1 = packpair(sac[i][2 * t][2], sac[i][2 * t][3]);
                uint2 w2 = packpair(sac[i][2 * t + 1][0], sac[i][2 * t + 1][1]);
                uint2 w3 = packpair(sac[i][2 * t + 1][2], sac[i][2 * t + 1][3]);
                ph[i][t][0] = w0.x; pl[i][t][0] = w0.y;
                ph[i][t][1] = w1.x; pl[i][t][1] = w1.y;
                ph[i][t][2] = w2.x; pl[i][t][2] = w2.y;
                ph[i][t][3] = w3.x; pl[i][t][3] = w3.y;
            }
        }

        // ---- O += P @ V (V frags shared across both m-frags) ----
        #pragma unroll
        for (int t = 0; t < 4; t++) {
            #pragma unroll
            for (int n = 0; n < 16; n++) {
                uint2 e0 = Vb[(8 * t + tig) * FV_S + 8 * n + gid];
                uint2 e1 = Vb[(8 * t + tig + 4) * FV_S + 8 * n + gid];
                uint32_t bh[2] = {e0.x, e1.x};
                uint32_t bl[2] = {e0.y, e1.y};
                #pragma unroll
                for (int i = 0; i < 2; i++) {
                    mma_bf16(oac[i][n], ph[i][t], bh);
                    mma_bf16(oac[i][n], pl[i][t], bh);
                    mma_bf16(oac[i][n], ph[i][t], bl);
                }
            }
        }

        if (kt + 1 < 32) {
            CP_WAIT0();
            __syncthreads();
        }
    }

    // ---- epilogue: O/l -> arp (F1) ----
    #pragma unroll
    for (int i = 0; i < 2; i++) {
        float rl0 = 1.f / lst[2 * i], rl1 = 1.f / lst[2 * i + 1];
        long long r0 = qrow0 + mrow + i * 16 + gid;
        uint2* op0 = arp + r0 * 384 + h * 64;
        uint2* op1 = op0 + 8LL * 384;
        #pragma unroll
        for (int n = 0; n < 16; n++) {
            op0[4 * n + tig] = packpair(oac[i][n][0] * rl0, oac[i][n][1] * rl0);
            op1[4 * n + tig] = packpair(oac[i][n][2] * rl1, oac[i][n][3] * rl1);
        }
    }
}

// ============================================================================
// row softmax + pack to F1 (cultural branch)
// ============================================================================
__global__ void __launch_bounds__(256) softmax_pack(const float* __restrict__ in,
                                                    uint2* __restrict__ out)
{
    const long long row = blockIdx.x;
    const float2* r = (const float2*)(in + row * S_LEN);
    uint2* o = out + row * (S_LEN / 2);
    const int tid = threadIdx.x;
    __shared__ float red[256];

    float2 v[4];
    float mx = -1e30f;
    #pragma unroll
    for (int i = 0; i < 4; i++) {
        v[i] = r[tid + i * 256];
        mx = fmaxf(mx, fmaxf(v[i].x, v[i].y));
    }
    red[tid] = mx; __syncthreads();
    for (int s = 128; s > 0; s >>= 1) {
        if (tid < s) red[tid] = fmaxf(red[tid], red[tid + s]);
        __syncthreads();
    }
    mx = red[0];
    __syncthreads();

    float sum = 0.f;
    #pragma unroll
    for (int i = 0; i < 4; i++) {
        v[i].x = __expf(v[i].x - mx);
        v[i].y = __expf(v[i].y - mx);
        sum += v[i].x + v[i].y;
    }
    red[tid] = sum; __syncthreads();
    for (int s = 128; s > 0; s >>= 1) {
        if (tid < s) red[tid] += red[tid + s];
        __syncthreads();
    }
    const float inv = 1.0f / red[0];
    #pragma unroll
    for (int i = 0; i < 4; i++)
        o[tid + i * 256] = packpair(v[i].x * inv, v[i].y * inv);
}

// ============================================================================
template <typename T>
static T* symaddr(const void* s) {
    void* p = nullptr;
    cudaGetSymbolAddress(&p, s);
    return (T*)p;
}

extern "C" void kernel_launch(void* const* d_in, const int* in_sizes, int n_in,
                              void* d_out, int out_size)
{
    const float* x    = (const float*)d_in[0];
    const float* cm   = (const float*)d_in[1];
    const float* am   = (const float*)d_in[2];
    const float* rq_w = (const float*)d_in[3];
    const float* rk_w = (const float*)d_in[4];
    const float* rv_w = (const float*)d_in[5];
    const float* ro_w = (const float*)d_in[6];
    const float* cq_w = (const float*)d_in[7];
    const float* ck_w = (const float*)d_in[8];
    const float* cv_w = (const float*)d_in[9];
    const float* co_w = (const float*)d_in[10];
    const float* rq_b = (const float*)d_in[11];
    const float* rk_b = (const float*)d_in[12];
    const float* rv_b = (const float*)d_in[13];
    const float* ro_b = (const float*)d_in[14];
    const float* cq_b = (const float*)d_in[15];
    const float* ck_b = (const float*)d_in[16];
    const float* cv_b = (const float*)d_in[17];
    const float* co_b = (const float*)d_in[18];
    const float* r_cb = (const float*)d_in[19];
    const float* c_cb = (const float*)d_in[20];
    const float* out_w = (const float*)d_in[21];
    const float* out_b = (const float*)d_in[22];
    float* out = (float*)d_out;

    uint2* xp    = symaddr<uint2>(g_xp);
    uint2* wqkvp = symaddr<uint2>(g_wqkvp);
    float* bqkv  = symaddr<float>(g_bqkv);
    float* qkv   = symaddr<float>(g_qkv);
    uint2* qkvp  = symaddr<uint2>(g_qkvp);
    uint2* vf2   = symaddr<uint2>(g_vf2);
    float* sc    = symaddr<float>(g_sc);
    uint2* scp   = symaddr<uint2>(g_scp);
    uint2* arp   = symaddr<uint2>(g_arp);
    uint2* acp   = symaddr<uint2>(g_acp);
    uint2* wop   = symaddr<uint2>(g_wop);
    uint2* outwp = symaddr<uint2>(g_outwp);
    uint2* catp  = symaddr<uint2>(g_catp);

    cudaFuncSetAttribute(flash_reg, cudaFuncAttributeMaxDynamicSharedMemorySize, FLASH_SMEM);

    dim3 blk(128);

    // ---- pack weights (F2) + biases ----
    {
        const int tot66 = 384 * 768;
        const float* ws[6] = {rq_w, rk_w, rv_w, cq_w, ck_w, cv_w};
        for (int i = 0; i < 6; i++)
            pack_f2<<<(tot66 + 255) / 256, 256>>>(ws[i], wqkvp, 768, NQKV, i * 768, tot66);
        pack_f2<<<(tot66 + 255) / 256, 256>>>(ro_w, wop, 768, 1536, 0, tot66);
        pack_f2<<<(tot66 + 255) / 256, 256>>>(co_w, wop, 768, 1536, 768, tot66);
        const int toto = 768 * 768;
        pack_f2<<<(toto + 255) / 256, 256>>>(out_w, outwp, 768, 768, 0, toto);
        fold_bias<<<(NQKV + 255) / 256, 256>>>(rq_b, rk_b, rv_b, cq_b, ck_b, cv_b,
                                               r_cb, c_cb, bqkv);
    }

    // ---- split x -> F1 ----
    {
        const int tp = M_TOT * 384;
        split_f1<<<(tp + 255) / 256, 256>>>(x, xp, tp);
    }

    // ---- fused QKV projection ----
    dim3 gq(NQKV / 64, M_TOT / 128, 1);
    gemm_bf3_nn<<<gq, blk>>>(xp, wqkvp, qkv, qkvp, bqkv,
                             E_DIM, 384, NQKV, NQKV, 2304,
                             0, 0, 0, 0, 0, 1);

    // ---- split V -> F2 ----
    {
        const int tv = B_SZ * 1024 * 1536;
        split_v<<<(tv + 255) / 256, 256>>>(qkv, vf2);
    }

    // ---- regular branch: flash-fused attention (4 warps, M=32/warp) ----
    {
        const float scale_r = 1.0f / sqrtf((float)HD_R);
        dim3 gf(16, B_SZ * NH_R);
        flash_reg<<<gf, 128, FLASH_SMEM>>>(qkvp, vf2, am, arp, scale_r);
    }

    // ---- cultural branch: two-pass ----
    const float scale_c = 1.0f / sqrtf((float)HD_C);
    dim3 gsc(S_LEN / 64, S_LEN / 128, B_SZ * NH_C);
    gemm_bf3_nt_scores<<<gsc, blk>>>(qkvp + 1152, qkvp + 1536, sc,
                                     am, cm, scale_c, HD_C, NH_C, 2304);
    softmax_pack<<<B_SZ * NH_C * S_LEN, 256>>>(sc, scp);
    dim3 gac(HD_C / 64, S_LEN / 128, B_SZ * NH_C);
    gemm_bf3_nn<<<gac, blk>>>(scp, vf2 + 768, nullptr, acp, nullptr,
                              S_LEN, 1024, 1536, 0, 384,
                              (long long)S_LEN * 1024,
                              (long long)1024 * 1536, HD_C,
                              (long long)S_LEN * 384, HD_C / 2, NH_C);

    // ---- output projections -> packed concat ----
    dim3 gp(E_DIM / 64, M_TOT / 128, 1);
    gemm_bf3_nn<<<gp, blk>>>(arp, wop, nullptr, catp, ro_b,
                             E_DIM, 384, 1536, 0, 768,
                             0, 0, 0, 0, 0, 1);
    gemm_bf3_nn<<<gp, blk>>>(acp, wop + 768, nullptr, catp + 384, co_b,
                             E_DIM, 384, 1536, 0, 768,
                             0, 0, 0, 0, 0, 1);

    // ---- final: [M,2E] @ [2E,E] + out_b -> fp32 out ----
    gemm_bf3_nn<<<gp, blk>>>(catp, outwp, out, nullptr, out_b,
                             2 * E_DIM, 768, 768, 768, 0,
                             0, 0, 0, 0, 0, 1);
}

// round 8
// speedup vs baseline: 1.3256x; 1.3256x over previous
#include <cuda_runtime.h>
#include <cuda_bf16.h>
#include <math.h>
#include <stdint.h>

#define S_LEN 2048
#define E_DIM 768
#define B_SZ  2
#define NH_R  6
#define NH_C  2
#define HD_R  128
#define HD_C  384
#define M_TOT 4096
#define NQKV  4608

// smem strides (uint2 units); stride mod 16 == 4 -> conflict-free LDS.64 frags
#define SP_A  20
#define SP_BN 68
#define SP_BT 20

// flash smem geometry (uint2 units)
#define FQ_S 68
#define FK_S 68
#define FV_S 132
#define FQ_SZ (128*FQ_S)
#define FK_SZ (64*FK_S)
#define FV_SZ (32*FV_S)
#define FLASH_SMEM ((FQ_SZ + 2*FK_SZ + 2*FV_SZ)*8 + 2*64*4)   // 207,360 B

// -------- scratch ------------------------------------------------------------
__device__ uint2 g_xp[(size_t)M_TOT*384];
__device__ uint2 g_wqkvp[(size_t)384*NQKV];
__device__ float g_bqkv[NQKV];
__device__ uint2 g_qkvp[(size_t)M_TOT*2304];
__device__ uint2 g_vf2[(size_t)B_SZ*1024*1536];
__device__ float g_sc[(size_t)B_SZ*NH_C*S_LEN*S_LEN];
__device__ uint2 g_scp[(size_t)B_SZ*NH_C*S_LEN*1024];
__device__ uint2 g_arp[(size_t)M_TOT*384];
__device__ uint2 g_acp[(size_t)M_TOT*384];
__device__ uint2 g_wop[(size_t)384*1536];
__device__ uint2 g_outwp[(size_t)768*768];
__device__ uint2 g_catp[(size_t)M_TOT*768];

// -------- helpers --------------------------------------------------------------
__device__ __forceinline__ uint32_t smem_u32(const void* p) {
    return (uint32_t)__cvta_generic_to_shared(p);
}
#define CP16(sa, ga) asm volatile("cp.async.cg.shared.global [%0], [%1], 16;" :: "r"(sa), "l"(ga))
#define CP_COMMIT()  asm volatile("cp.async.commit_group;" ::: "memory")
#define CP_WAIT0()   asm volatile("cp.async.wait_group 0;" ::: "memory")

__device__ __forceinline__ uint32_t bf2w(float a, float b) {
    __nv_bfloat162 t;
    t.x = __float2bfloat16(a); t.y = __float2bfloat16(b);
    return *reinterpret_cast<uint32_t*>(&t);
}
__device__ __forceinline__ uint2 packpair(float e, float o) {
    __nv_bfloat16 he = __float2bfloat16(e);
    __nv_bfloat16 ho = __float2bfloat16(o);
    float le = e - __bfloat162float(he);
    float lo = o - __bfloat162float(ho);
    uint2 r;
    __nv_bfloat162 th; th.x = he; th.y = ho;
    r.x = *reinterpret_cast<uint32_t*>(&th);
    r.y = bf2w(le, lo);
    return r;
}

__device__ __forceinline__ void mma_bf16(float* c, const uint32_t* a, const uint32_t* b) {
    asm volatile(
        "mma.sync.aligned.m16n8k16.row.col.f32.bf16.bf16.f32 "
        "{%0,%1,%2,%3}, {%4,%5,%6,%7}, {%8,%9}, {%0,%1,%2,%3};"
        : "+f"(c[0]), "+f"(c[1]), "+f"(c[2]), "+f"(c[3])
        : "r"(a[0]), "r"(a[1]), "r"(a[2]), "r"(a[3]), "r"(b[0]), "r"(b[1]));
}

// ============================================================================
// small packing kernels
// ============================================================================
__global__ void pack_f2(const float* __restrict__ src, uint2* __restrict__ dst,
                        int Nsrc, int dstN, int col_off, int total)
{
    int idx = blockIdx.x * 256 + threadIdx.x;
    if (idx >= total) return;
    int p = idx / Nsrc, n = idx % Nsrc;
    dst[(long long)p * dstN + col_off + n] =
        packpair(src[(long long)(2 * p) * Nsrc + n], src[(long long)(2 * p + 1) * Nsrc + n]);
}

__global__ void fold_bias(const float* b0, const float* b1, const float* b2,
                          const float* b3, const float* b4, const float* b5,
                          const float* rcb, const float* ccb, float* Bv)
{
    int idx = blockIdx.x * 256 + threadIdx.x;
    if (idx >= NQKV) return;
    int blk = idx / E_DIM, c = idx % E_DIM;
    const float* bs;
    switch (blk) {
        case 0: bs = b0; break; case 1: bs = b1; break; case 2: bs = b2; break;
        case 3: bs = b3; break; case 4: bs = b4; break; default: bs = b5; break;
    }
    float v = bs[c];
    if (blk == 0) v += rcb[c];
    if (blk == 3) v += ccb[c];
    Bv[idx] = v;
}

__global__ void split_f1(const float* __restrict__ src, uint2* __restrict__ dst, int totalPairs)
{
    int idx = blockIdx.x * 256 + threadIdx.x;
    if (idx >= totalPairs) return;
    float2 f = ((const float2*)src)[idx];
    dst[idx] = packpair(f.x, f.y);
}

// V F2 planes reconstructed from packed qkvp (hi+lo), no fp32 buffer needed
__global__ void split_v(const uint2* __restrict__ qkvp, uint2* __restrict__ v)
{
    int idx = blockIdx.x * 256 + threadIdx.x;
    const int total = B_SZ * 1024 * 1536;
    if (idx >= total) return;
    int b = idx / (1024 * 1536);
    int r = idx % (1024 * 1536);
    int p = r / 1536, n = r % 1536;
    int col = (n < 768) ? (1536 + n) : (3072 + n);
    int cp = col >> 1, half = col & 1;
    const uint2 w0 = qkvp[(size_t)(b * 2048 + 2 * p) * 2304 + cp];
    const uint2 w1 = qkvp[(size_t)(b * 2048 + 2 * p + 1) * 2304 + cp];
    __nv_bfloat162 h0 = *(const __nv_bfloat162*)&w0.x;
    __nv_bfloat162 l0 = *(const __nv_bfloat162*)&w0.y;
    __nv_bfloat162 h1 = *(const __nv_bfloat162*)&w1.x;
    __nv_bfloat162 l1 = *(const __nv_bfloat162*)&w1.y;
    float e = half ? (__bfloat162float(h0.y) + __bfloat162float(l0.y))
                   : (__bfloat162float(h0.x) + __bfloat162float(l0.x));
    float o = half ? (__bfloat162float(h1.y) + __bfloat162float(l1.y))
                   : (__bfloat162float(h1.x) + __bfloat162float(l1.x));
    v[idx] = packpair(e, o);
}

// ============================================================================
// NN GEMM, bf16x3 (unchanged)
// ============================================================================
__global__ void __launch_bounds__(128) gemm_bf3_nn(
    const uint2* __restrict__ A, const uint2* __restrict__ B,
    float* __restrict__ Cf, uint2* __restrict__ Cp,
    const float* __restrict__ bias,
    int K, int lda2, int ldbN, int ldc, int ldc2,
    long long sA2, long long sBb, long long sBh,
    long long sCpb, long long sCph, int nh)
{
    __shared__ uint2 As[128 * SP_A];
    __shared__ uint2 Bs[16 * SP_BN];
    const int tid = threadIdx.x;
    const int wid = tid >> 5, lane = tid & 31;
    const int gid = lane >> 2, tig = lane & 3;
    const int wm = wid >> 1, wn = wid & 1;
    const int z = blockIdx.z, b = z / nh, h = z % nh;
    const uint2* Ap = A + (long long)z * sA2;
    const uint2* Bp = B + (long long)b * sBb + (long long)h * sBh;
    const int row0 = blockIdx.y * 128, col0 = blockIdx.x * 64;

    uint4 pa[8], pbuf[4];
    #pragma unroll
    for (int it = 0; it < 8; it++) {
        int lin = it * 128 + tid; int m = lin >> 3, p4 = (lin & 7) << 1;
        pa[it] = *(const uint4*)(Ap + (long long)(row0 + m) * lda2 + p4);
    }
    #pragma unroll
    for (int it = 0; it < 4; it++) {
        int lin = it * 128 + tid; int p = lin >> 5, n2 = (lin & 31) << 1;
        pbuf[it] = *(const uint4*)(Bp + (long long)p * ldbN + col0 + n2);
    }

    float acc[4][4][4] = {};

    for (int k0 = 0; k0 < K; k0 += 32) {
        #pragma unroll
        for (int it = 0; it < 8; it++) {
            int lin = it * 128 + tid; int m = lin >> 3, p4 = (lin & 7) << 1;
            *(uint4*)&As[m * SP_A + p4] = pa[it];
        }
        #pragma unroll
        for (int it = 0; it < 4; it++) {
            int lin = it * 128 + tid; int p = lin >> 5, n2 = (lin & 31) << 1;
            *(uint4*)&Bs[p * SP_BN + n2] = pbuf[it];
        }
        __syncthreads();
        if (k0 + 32 < K) {
            int k02 = (k0 + 32) >> 1;
            #pragma unroll
            for (int it = 0; it < 8; it++) {
                int lin = it * 128 + tid; int m = lin >> 3, p4 = (lin & 7) << 1;
                pa[it] = *(const uint4*)(Ap + (long long)(row0 + m) * lda2 + k02 + p4);
            }
            #pragma unroll
            for (int it = 0; it < 4; it++) {
                int lin = it * 128 + tid; int p = lin >> 5, n2 = (lin & 31) << 1;
                pbuf[it] = *(const uint4*)(Bp + (long long)(k02 + p) * ldbN + col0 + n2);
            }
        }
        #pragma unroll
        for (int pb2 = 0; pb2 < 16; pb2 += 8) {
            uint32_t bh[4][2], bl[4][2];
            #pragma unroll
            for (int j = 0; j < 4; j++) {
                int n = wn * 32 + j * 8 + gid;
                uint2 e0 = Bs[(pb2 + tig) * SP_BN + n];
                uint2 e1 = Bs[(pb2 + tig + 4) * SP_BN + n];
                bh[j][0] = e0.x; bl[j][0] = e0.y;
                bh[j][1] = e1.x; bl[j][1] = e1.y;
            }
            #pragma unroll
            for (int i = 0; i < 4; i++) {
                int mb = wm * 64 + i * 16 + gid;
                uint2 a0 = As[mb * SP_A + pb2 + tig];
                uint2 a1 = As[(mb + 8) * SP_A + pb2 + tig];
                uint2 a2 = As[mb * SP_A + pb2 + tig + 4];
                uint2 a3 = As[(mb + 8) * SP_A + pb2 + tig + 4];
                uint32_t ah[4] = {a0.x, a1.x, a2.x, a3.x};
                uint32_t al[4] = {a0.y, a1.y, a2.y, a3.y};
                #pragma unroll
                for (int j = 0; j < 4; j++) {
                    mma_bf16(acc[i][j], ah, bh[j]);
                    mma_bf16(acc[i][j], al, bh[j]);
                    mma_bf16(acc[i][j], ah, bl[j]);
                }
            }
        }
        __syncthreads();
    }

    uint2* Cpb = Cp ? (Cp + (long long)b * sCpb + (long long)h * sCph) : nullptr;
    #pragma unroll
    for (int i = 0; i < 4; i++) {
        int r0 = row0 + wm * 64 + i * 16 + gid;
        #pragma unroll
        for (int j = 0; j < 4; j++) {
            int c = col0 + wn * 32 + j * 8 + tig * 2;
            float b0 = 0.f, b1 = 0.f;
            if (bias) { b0 = bias[c]; b1 = bias[c + 1]; }
            float v00 = acc[i][j][0] + b0, v01 = acc[i][j][1] + b1;
            float v10 = acc[i][j][2] + b0, v11 = acc[i][j][3] + b1;
            if (Cf) {
                float2 t0 = {v00, v01}, t1 = {v10, v11};
                *(float2*)(Cf + (long long)r0 * ldc + c) = t0;
                *(float2*)(Cf + (long long)(r0 + 8) * ldc + c) = t1;
            }
            if (Cpb) {
                Cpb[(long long)r0 * ldc2 + (c >> 1)] = packpair(v00, v01);
                Cpb[(long long)(r0 + 8) * ldc2 + (c >> 1)] = packpair(v10, v11);
            }
        }
    }
}

// ============================================================================
// NT scores GEMM (cultural branch only; unchanged)
// ============================================================================
__global__ void __launch_bounds__(128) gemm_bf3_nt_scores(
    const uint2* __restrict__ Qb, const uint2* __restrict__ Kb,
    float* __restrict__ Sc,
    const float* __restrict__ am, const float* __restrict__ cm,
    float scale, int hd, int nh, int lda2)
{
    __shared__ uint2 As[128 * SP_A];
    __shared__ uint2 Bs[64 * SP_BT];
    const int tid = threadIdx.x;
    const int wid = tid >> 5, lane = tid & 31;
    const int gid = lane >> 2, tig = lane & 3;
    const int wm = wid >> 1, wn = wid & 1;
    const int z = blockIdx.z, b = z / nh, h = z % nh;
    const int hp = hd >> 1;
    const uint2* Qp = Qb + (long long)b * S_LEN * lda2 + h * hp;
    const uint2* Kp = Kb + (long long)b * S_LEN * lda2 + h * hp;
    float* Cpt = Sc + (long long)z * S_LEN * S_LEN;
    const int row0 = blockIdx.y * 128, col0 = blockIdx.x * 64;

    uint4 pa[8], pbuf[4];
    #pragma unroll
    for (int it = 0; it < 8; it++) {
        int lin = it * 128 + tid; int m = lin >> 3, p4 = (lin & 7) << 1;
        pa[it] = *(const uint4*)(Qp + (long long)(row0 + m) * lda2 + p4);
    }
    #pragma unroll
    for (int it = 0; it < 4; it++) {
        int lin = it * 128 + tid; int n = lin >> 3, p4 = (lin & 7) << 1;
        pbuf[it] = *(const uint4*)(Kp + (long long)(col0 + n) * lda2 + p4);
    }

    float acc[4][4][4] = {};

    for (int k0 = 0; k0 < hd; k0 += 32) {
        #pragma unroll
        for (int it = 0; it < 8; it++) {
            int lin = it * 128 + tid; int m = lin >> 3, p4 = (lin & 7) << 1;
            *(uint4*)&As[m * SP_A + p4] = pa[it];
        }
        #pragma unroll
        for (int it = 0; it < 4; it++) {
            int lin = it * 128 + tid; int n = lin >> 3, p4 = (lin & 7) << 1;
            *(uint4*)&Bs[n * SP_BT + p4] = pbuf[it];
        }
        __syncthreads();
        if (k0 + 32 < hd) {
            int k02 = (k0 + 32) >> 1;
            #pragma unroll
            for (int it = 0; it < 8; it++) {
                int lin = it * 128 + tid; int m = lin >> 3, p4 = (lin & 7) << 1;
                pa[it] = *(const uint4*)(Qp + (long long)(row0 + m) * lda2 + k02 + p4);
            }
            #pragma unroll
            for (int it = 0; it < 4; it++) {
                int lin = it * 128 + tid; int n = lin >> 3, p4 = (lin & 7) << 1;
                pbuf[it] = *(const uint4*)(Kp + (long long)(col0 + n) * lda2 + k02 + p4);
            }
        }
        #pragma unroll
        for (int pb2 = 0; pb2 < 16; pb2 += 8) {
            uint32_t bh[4][2], bl[4][2];
            #pragma unroll
            for (int j = 0; j < 4; j++) {
                int n = wn * 32 + j * 8 + gid;
                uint2 e0 = Bs[n * SP_BT + pb2 + tig];
                uint2 e1 = Bs[n * SP_BT + pb2 + tig + 4];
                bh[j][0] = e0.x; bl[j][0] = e0.y;
                bh[j][1] = e1.x; bl[j][1] = e1.y;
            }
            #pragma unroll
            for (int i = 0; i < 4; i++) {
                int mb = wm * 64 + i * 16 + gid;
                uint2 a0 = As[mb * SP_A + pb2 + tig];
                uint2 a1 = As[(mb + 8) * SP_A + pb2 + tig];
                uint2 a2 = As[mb * SP_A + pb2 + tig + 4];
                uint2 a3 = As[(mb + 8) * SP_A + pb2 + tig + 4];
                uint32_t ah[4] = {a0.x, a1.x, a2.x, a3.x};
                uint32_t al[4] = {a0.y, a1.y, a2.y, a3.y};
                #pragma unroll
                for (int j = 0; j < 4; j++) {
                    mma_bf16(acc[i][j], ah, bh[j]);
                    mma_bf16(acc[i][j], al, bh[j]);
                    mma_bf16(acc[i][j], ah, bl[j]);
                }
            }
        }
        __syncthreads();
    }

    #pragma unroll
    for (int i = 0; i < 4; i++) {
        int t0 = row0 + wm * 64 + i * 16 + gid;
        #pragma unroll
        for (int j = 0; j < 4; j++) {
            int s = col0 + wn * 32 + j * 8 + tig * 2;
            float m0 = am[b * S_LEN + s], m1 = am[b * S_LEN + s + 1];
            float n0 = m0, n1 = m1;
            if (cm) {
                const float* cmr0 = cm + ((long long)b * S_LEN + t0) * S_LEN;
                const float* cmr1 = cmr0 + 8LL * S_LEN;
                m0 += cmr0[s]; m1 += cmr0[s + 1];
                n0 += cmr1[s]; n1 += cmr1[s + 1];
            }
            float2 v0 = { acc[i][j][0] * scale + m0, acc[i][j][1] * scale + m1 };
            float2 v1 = { acc[i][j][2] * scale + n0, acc[i][j][3] * scale + n1 };
            *(float2*)(Cpt + (long long)t0 * S_LEN + s) = v0;
            *(float2*)(Cpt + (long long)(t0 + 8) * S_LEN + s) = v1;
        }
    }
}

// ============================================================================
// Flash-fused regular branch (round-6 8-warp version, proven)
// ============================================================================
__global__ void __launch_bounds__(256, 1) flash_reg(
    const uint2* __restrict__ qkvp, const uint2* __restrict__ vf2,
    const float* __restrict__ am, uint2* __restrict__ arp, float scale)
{
    extern __shared__ uint2 sm[];
    uint2* Qs = sm;
    uint2* Ks = Qs + FQ_SZ;
    uint2* Vs = Ks + 2 * FK_SZ;
    float* ams = (float*)(Vs + 2 * FV_SZ);

    const int tid = threadIdx.x, wid = tid >> 5, lane = tid & 31;
    const int gid = lane >> 2, tig = lane & 3;
    const int qt = blockIdx.x;
    const int z = blockIdx.y, b = z / NH_R, h = z % NH_R;

    const long long qrow0 = (long long)b * S_LEN + qt * 128;
    const uint2* Qg = qkvp + qrow0 * 2304 + h * 64;
    const uint2* Kg = qkvp + (long long)b * S_LEN * 2304 + 384 + h * 64;
    const uint2* Vg = vf2 + (long long)b * 1024 * 1536 + h * 128;
    const float* amb = am + (long long)b * S_LEN;

    #pragma unroll
    for (int it = 0; it < 16; it++) {
        int lin = it * 256 + tid;
        int r = lin >> 5, p2 = (lin & 31) << 1;
        CP16(smem_u32(&Qs[r * FQ_S + p2]), Qg + (long long)r * 2304 + p2);
    }
    {
        #pragma unroll
        for (int it = 0; it < 8; it++) {
            int lin = it * 256 + tid;
            int r = lin >> 5, p2 = (lin & 31) << 1;
            CP16(smem_u32(&Ks[r * FK_S + p2]), Kg + (long long)r * 2304 + p2);
        }
        #pragma unroll
        for (int it = 0; it < 8; it++) {
            int lin = it * 256 + tid;
            int p = lin >> 6, n2 = (lin & 63) << 1;
            CP16(smem_u32(&Vs[p * FV_S + n2]), Vg + (long long)p * 1536 + n2);
        }
        if (tid < 16) CP16(smem_u32(&ams[tid * 4]), amb + tid * 4);
    }
    CP_COMMIT();

    float oac[16][4] = {};
    float m0 = -1e30f, m1 = -1e30f, l0 = 0.f, l1 = 0.f;
    const int mrow = wid * 16;

    CP_WAIT0();
    __syncthreads();

    for (int kt = 0; kt < 32; kt++) {
        if (kt + 1 < 32) {
            int nb = (kt + 1) & 1;
            uint2* Kd = Ks + nb * FK_SZ;
            uint2* Vd = Vs + nb * FV_SZ;
            #pragma unroll
            for (int it = 0; it < 8; it++) {
                int lin = it * 256 + tid;
                int r = lin >> 5, p2 = (lin & 31) << 1;
                CP16(smem_u32(&Kd[r * FK_S + p2]),
                     Kg + (long long)((kt + 1) * 64 + r) * 2304 + p2);
            }
            #pragma unroll
            for (int it = 0; it < 8; it++) {
                int lin = it * 256 + tid;
                int p = lin >> 6, n2 = (lin & 63) << 1;
                CP16(smem_u32(&Vd[p * FV_S + n2]),
                     Vg + (long long)((kt + 1) * 32 + p) * 1536 + n2);
            }
            if (tid < 16)
                CP16(smem_u32(&ams[nb * 64 + tid * 4]), amb + (kt + 1) * 64 + tid * 4);
            CP_COMMIT();
        }

        const uint2* Kb = Ks + (kt & 1) * FK_SZ;
        const uint2* Vb = Vs + (kt & 1) * FV_SZ;
        const float* amc = ams + (kt & 1) * 64;

        float sac[8][4] = {};
        #pragma unroll
        for (int t = 0; t < 8; t++) {
            uint2 a0 = Qs[(mrow + gid) * FQ_S + 8 * t + tig];
            uint2 a1 = Qs[(mrow + gid + 8) * FQ_S + 8 * t + tig];
            uint2 a2 = Qs[(mrow + gid) * FQ_S + 8 * t + tig + 4];
            uint2 a3 = Qs[(mrow + gid + 8) * FQ_S + 8 * t + tig + 4];
            uint32_t ah[4] = {a0.x, a1.x, a2.x, a3.x};
            uint32_t al[4] = {a0.y, a1.y, a2.y, a3.y};
            #pragma unroll
            for (int j = 0; j < 8; j++) {
                uint2 e0 = Kb[(8 * j + gid) * FK_S + 8 * t + tig];
                uint2 e1 = Kb[(8 * j + gid) * FK_S + 8 * t + tig + 4];
                uint32_t bh[2] = {e0.x, e1.x};
                uint32_t bl[2] = {e0.y, e1.y};
                mma_bf16(sac[j], ah, bh);
                mma_bf16(sac[j], al, bh);
                mma_bf16(sac[j], ah, bl);
            }
        }

        float mx0 = -1e30f, mx1 = -1e30f;
        #pragma unroll
        for (int j = 0; j < 8; j++) {
            float a0 = amc[8 * j + 2 * tig], a1 = amc[8 * j + 2 * tig + 1];
            sac[j][0] = sac[j][0] * scale + a0;
            sac[j][1] = sac[j][1] * scale + a1;
            sac[j][2] = sac[j][2] * scale + a0;
            sac[j][3] = sac[j][3] * scale + a1;
            mx0 = fmaxf(mx0, fmaxf(sac[j][0], sac[j][1]));
            mx1 = fmaxf(mx1, fmaxf(sac[j][2], sac[j][3]));
        }
        mx0 = fmaxf(mx0, __shfl_xor_sync(0xffffffffu, mx0, 1));
        mx0 = fmaxf(mx0, __shfl_xor_sync(0xffffffffu, mx0, 2));
        mx1 = fmaxf(mx1, __shfl_xor_sync(0xffffffffu, mx1, 1));
        mx1 = fmaxf(mx1, __shfl_xor_sync(0xffffffffu, mx1, 2));
        float mn0 = fmaxf(m0, mx0), mn1 = fmaxf(m1, mx1);
        float sc0 = __expf(m0 - mn0), sc1 = __expf(m1 - mn1);
        float ps0 = 0.f, ps1 = 0.f;
        #pragma unroll
        for (int j = 0; j < 8; j++) {
            sac[j][0] = __expf(sac[j][0] - mn0);
            sac[j][1] = __expf(sac[j][1] - mn0);
            sac[j][2] = __expf(sac[j][2] - mn1);
            sac[j][3] = __expf(sac[j][3] - mn1);
            ps0 += sac[j][0] + sac[j][1];
            ps1 += sac[j][2] + sac[j][3];
        }
        ps0 += __shfl_xor_sync(0xffffffffu, ps0, 1);
        ps0 += __shfl_xor_sync(0xffffffffu, ps0, 2);
        ps1 += __shfl_xor_sync(0xffffffffu, ps1, 1);
        ps1 += __shfl_xor_sync(0xffffffffu, ps1, 2);
        l0 = l0 * sc0 + ps0;
        l1 = l1 * sc1 + ps1;
        m0 = mn0; m1 = mn1;

        #pragma unroll
        for (int n = 0; n < 16; n++) {
            oac[n][0] *= sc0; oac[n][1] *= sc0;
            oac[n][2] *= sc1; oac[n][3] *= sc1;
        }

        uint32_t ph[4][4], pl[4][4];
        #pragma unroll
        for (int t = 0; t < 4; t++) {
            uint2 w0 = packpair(sac[2 * t][0], sac[2 * t][1]);
            uint2 w1 = packpair(sac[2 * t][2], sac[2 * t][3]);
            uint2 w2 = packpair(sac[2 * t + 1][0], sac[2 * t + 1][1]);
            uint2 w3 = packpair(sac[2 * t + 1][2], sac[2 * t + 1][3]);
            ph[t][0] = w0.x; pl[t][0] = w0.y;
            ph[t][1] = w1.x; pl[t][1] = w1.y;
            ph[t][2] = w2.x; pl[t][2] = w2.y;
            ph[t][3] = w3.x; pl[t][3] = w3.y;
        }

        #pragma unroll
        for (int t = 0; t < 4; t++) {
            #pragma unroll
            for (int n = 0; n < 16; n++) {
                uint2 e0 = Vb[(8 * t + tig) * FV_S + 8 * n + gid];
                uint2 e1 = Vb[(8 * t + tig + 4) * FV_S + 8 * n + gid];
                uint32_t bh[2] = {e0.x, e1.x};
                uint32_t bl[2] = {e0.y, e1.y};
                mma_bf16(oac[n], ph[t], bh);
                mma_bf16(oac[n], pl[t], bh);
                mma_bf16(oac[n], ph[t], bl);
            }
        }

        if (kt + 1 < 32) {
            CP_WAIT0();
            __syncthreads();
        }
    }

    float rl0 = 1.f / l0, rl1 = 1.f / l1;
    long long r0 = qrow0 + mrow + gid;
    uint2* op0 = arp + r0 * 384 + h * 64;
    uint2* op1 = op0 + 8LL * 384;
    #pragma unroll
    for (int n = 0; n < 16; n++) {
        op0[4 * n + tig] = packpair(oac[n][0] * rl0, oac[n][1] * rl0);
        op1[4 * n + tig] = packpair(oac[n][2] * rl1, oac[n][3] * rl1);
    }
}

// ============================================================================
// row softmax + pack to F1 (cultural branch)
// ============================================================================
__global__ void __launch_bounds__(256) softmax_pack(const float* __restrict__ in,
                                                    uint2* __restrict__ out)
{
    const long long row = blockIdx.x;
    const float2* r = (const float2*)(in + row * S_LEN);
    uint2* o = out + row * (S_LEN / 2);
    const int tid = threadIdx.x;
    __shared__ float red[256];

    float2 v[4];
    float mx = -1e30f;
    #pragma unroll
    for (int i = 0; i < 4; i++) {
        v[i] = r[tid + i * 256];
        mx = fmaxf(mx, fmaxf(v[i].x, v[i].y));
    }
    red[tid] = mx; __syncthreads();
    for (int s = 128; s > 0; s >>= 1) {
        if (tid < s) red[tid] = fmaxf(red[tid], red[tid + s]);
        __syncthreads();
    }
    mx = red[0];
    __syncthreads();

    float sum = 0.f;
    #pragma unroll
    for (int i = 0; i < 4; i++) {
        v[i].x = __expf(v[i].x - mx);
        v[i].y = __expf(v[i].y - mx);
        sum += v[i].x + v[i].y;
    }
    red[tid] = sum; __syncthreads();
    for (int s = 128; s > 0; s >>= 1) {
        if (tid < s) red[tid] += red[tid + s];
        __syncthreads();
    }
    const float inv = 1.0f / red[0];
    #pragma unroll
    for (int i = 0; i < 4; i++)
        o[tid + i * 256] = packpair(v[i].x * inv, v[i].y * inv);
}

// ============================================================================
template <typename T>
static T* symaddr(const void* s) {
    void* p = nullptr;
    cudaGetSymbolAddress(&p, s);
    return (T*)p;
}

extern "C" void kernel_launch(void* const* d_in, const int* in_sizes, int n_in,
                              void* d_out, int out_size)
{
    const float* x    = (const float*)d_in[0];
    const float* cm   = (const float*)d_in[1];
    const float* am   = (const float*)d_in[2];
    const float* rq_w = (const float*)d_in[3];
    const float* rk_w = (const float*)d_in[4];
    const float* rv_w = (const float*)d_in[5];
    const float* ro_w = (const float*)d_in[6];
    const float* cq_w = (const float*)d_in[7];
    const float* ck_w = (const float*)d_in[8];
    const float* cv_w = (const float*)d_in[9];
    const float* co_w = (const float*)d_in[10];
    const float* rq_b = (const float*)d_in[11];
    const float* rk_b = (const float*)d_in[12];
    const float* rv_b = (const float*)d_in[13];
    const float* ro_b = (const float*)d_in[14];
    const float* cq_b = (const float*)d_in[15];
    const float* ck_b = (const float*)d_in[16];
    const float* cv_b = (const float*)d_in[17];
    const float* co_b = (const float*)d_in[18];
    const float* r_cb = (const float*)d_in[19];
    const float* c_cb = (const float*)d_in[20];
    const float* out_w = (const float*)d_in[21];
    const float* out_b = (const float*)d_in[22];
    float* out = (float*)d_out;

    uint2* xp    = symaddr<uint2>(g_xp);
    uint2* wqkvp = symaddr<uint2>(g_wqkvp);
    float* bqkv  = symaddr<float>(g_bqkv);
    uint2* qkvp  = symaddr<uint2>(g_qkvp);
    uint2* vf2   = symaddr<uint2>(g_vf2);
    float* sc    = symaddr<float>(g_sc);
    uint2* scp   = symaddr<uint2>(g_scp);
    uint2* arp   = symaddr<uint2>(g_arp);
    uint2* acp   = symaddr<uint2>(g_acp);
    uint2* wop   = symaddr<uint2>(g_wop);
    uint2* outwp = symaddr<uint2>(g_outwp);
    uint2* catp  = symaddr<uint2>(g_catp);

    cudaFuncSetAttribute(flash_reg, cudaFuncAttributeMaxDynamicSharedMemorySize, FLASH_SMEM);

    // side stream + fork/join events (capture-legal pattern); intentionally not
    // destroyed (host objects only; kernel_launch runs a handful of times)
    cudaStream_t s2;
    cudaStreamCreateWithFlags(&s2, cudaStreamNonBlocking);
    cudaEvent_t evFork, evJoin;
    cudaEventCreateWithFlags(&evFork, cudaEventDisableTiming);
    cudaEventCreateWithFlags(&evJoin, cudaEventDisableTiming);

    dim3 blk(128);

    // ---- pack weights (F2) + biases ----
    {
        const int tot66 = 384 * 768;
        const float* ws[6] = {rq_w, rk_w, rv_w, cq_w, ck_w, cv_w};
        for (int i = 0; i < 6; i++)
            pack_f2<<<(tot66 + 255) / 256, 256>>>(ws[i], wqkvp, 768, NQKV, i * 768, tot66);
        pack_f2<<<(tot66 + 255) / 256, 256>>>(ro_w, wop, 768, 1536, 0, tot66);
        pack_f2<<<(tot66 + 255) / 256, 256>>>(co_w, wop, 768, 1536, 768, tot66);
        const int toto = 768 * 768;
        pack_f2<<<(toto + 255) / 256, 256>>>(out_w, outwp, 768, 768, 0, toto);
        fold_bias<<<(NQKV + 255) / 256, 256>>>(rq_b, rk_b, rv_b, cq_b, ck_b, cv_b,
                                               r_cb, c_cb, bqkv);
    }

    // ---- split x -> F1 ----
    {
        const int tp = M_TOT * 384;
        split_f1<<<(tp + 255) / 256, 256>>>(x, xp, tp);
    }

    // ---- fused QKV projection (packed output only) ----
    dim3 gq(NQKV / 64, M_TOT / 128, 1);
    gemm_bf3_nn<<<gq, blk>>>(xp, wqkvp, nullptr, qkvp, bqkv,
                             E_DIM, 384, NQKV, 0, 2304,
                             0, 0, 0, 0, 0, 1);

    // ---- split V -> F2 (from packed qkvp) ----
    {
        const int tv = B_SZ * 1024 * 1536;
        split_v<<<(tv + 255) / 256, 256>>>(qkvp, vf2);
    }

    // ---- fork: cultural branch on side stream ----
    cudaEventRecord(evFork, 0);
    cudaStreamWaitEvent(s2, evFork, 0);

    // main stream: regular branch flash + its o-projection
    {
        const float scale_r = 1.0f / sqrtf((float)HD_R);
        dim3 gf(16, B_SZ * NH_R);
        flash_reg<<<gf, 256, FLASH_SMEM>>>(qkvp, vf2, am, arp, scale_r);
        dim3 gp(E_DIM / 64, M_TOT / 128, 1);
        gemm_bf3_nn<<<gp, blk>>>(arp, wop, nullptr, catp, ro_b,
                                 E_DIM, 384, 1536, 0, 768,
                                 0, 0, 0, 0, 0, 1);
    }

    // side stream: cultural two-pass + its o-projection
    {
        const float scale_c = 1.0f / sqrtf((float)HD_C);
        dim3 gsc(S_LEN / 64, S_LEN / 128, B_SZ * NH_C);
        gemm_bf3_nt_scores<<<gsc, blk, 0, s2>>>(qkvp + 1152, qkvp + 1536, sc,
                                                am, cm, scale_c, HD_C, NH_C, 2304);
        softmax_pack<<<B_SZ * NH_C * S_LEN, 256, 0, s2>>>(sc, scp);
        dim3 gac(HD_C / 64, S_LEN / 128, B_SZ * NH_C);
        gemm_bf3_nn<<<gac, blk, 0, s2>>>(scp, vf2 + 768, nullptr, acp, nullptr,
                                         S_LEN, 1024, 1536, 0, 384,
                                         (long long)S_LEN * 1024,
                                         (long long)1024 * 1536, HD_C,
                                         (long long)S_LEN * 384, HD_C / 2, NH_C);
        dim3 gp(E_DIM / 64, M_TOT / 128, 1);
        gemm_bf3_nn<<<gp, blk, 0, s2>>>(acp, wop + 768, nullptr, catp + 384, co_b,
                                        E_DIM, 384, 1536, 0, 768,
                                        0, 0, 0, 0, 0, 1);
    }

    // ---- join ----
    cudaEventRecord(evJoin, s2);
    cudaStreamWaitEvent(0, evJoin, 0);

    // ---- final: [M,2E] @ [2E,E] + out_b -> fp32 out ----
    dim3 gp(E_DIM / 64, M_TOT / 128, 1);
    gemm_bf3_nn<<<gp, blk>>>(catp, outwp, out, nullptr, out_b,
                             2 * E_DIM, 768, 768, 768, 0,
                             0, 0, 0, 0, 0, 1);
}

// round 9
// speedup vs baseline: 1.3379x; 1.0092x over previous
#include <cuda_runtime.h>
#include <cuda_bf16.h>
#include <math.h>
#include <stdint.h>

#define S_LEN 2048
#define E_DIM 768
#define B_SZ  2
#define NH_R  6
#define NH_C  2
#define HD_R  128
#define HD_C  384
#define M_TOT 4096
#define NQKV  4608

// smem strides (uint2 units); stride mod 16 == 4 -> conflict-free LDS.64 frags
#define SP_A  20
#define SP_BN 68
#define SP_BT 20

// flash smem geometry (uint2 units)
#define FQ_S 68
#define FK_S 68
#define FV_S 132
#define FQ_SZ (128*FQ_S)
#define FK_SZ (64*FK_S)
#define FV_SZ (32*FV_S)
#define FLASH_SMEM ((FQ_SZ + 2*FK_SZ + 2*FV_SZ)*8 + 2*64*4)   // 207,360 B

// -------- scratch ------------------------------------------------------------
__device__ uint2 g_xp[(size_t)M_TOT*384];
__device__ uint2 g_wqkvp[(size_t)384*NQKV];
__device__ float g_bqkv[NQKV];
__device__ uint2 g_qkvp[(size_t)M_TOT*2304];
__device__ uint2 g_vf2[(size_t)B_SZ*1024*1536];
__device__ float g_sc[(size_t)B_SZ*NH_C*S_LEN*S_LEN];
__device__ uint2 g_scp[(size_t)B_SZ*NH_C*S_LEN*1024];
__device__ uint2 g_arp[(size_t)M_TOT*384];
__device__ uint2 g_acp[(size_t)M_TOT*384];
__device__ uint2 g_wop[(size_t)384*1536];
__device__ uint2 g_outwp[(size_t)768*768];
__device__ uint2 g_catp[(size_t)M_TOT*768];

// -------- helpers --------------------------------------------------------------
__device__ __forceinline__ uint32_t smem_u32(const void* p) {
    return (uint32_t)__cvta_generic_to_shared(p);
}
#define CP16(sa, ga) asm volatile("cp.async.cg.shared.global [%0], [%1], 16;" :: "r"(sa), "l"(ga))
#define CP_COMMIT()  asm volatile("cp.async.commit_group;" ::: "memory")
#define CP_WAIT0()   asm volatile("cp.async.wait_group 0;" ::: "memory")

__device__ __forceinline__ uint32_t bf2w(float a, float b) {
    __nv_bfloat162 t;
    t.x = __float2bfloat16(a); t.y = __float2bfloat16(b);
    return *reinterpret_cast<uint32_t*>(&t);
}
__device__ __forceinline__ uint2 packpair(float e, float o) {
    __nv_bfloat16 he = __float2bfloat16(e);
    __nv_bfloat16 ho = __float2bfloat16(o);
    float le = e - __bfloat162float(he);
    float lo = o - __bfloat162float(ho);
    uint2 r;
    __nv_bfloat162 th; th.x = he; th.y = ho;
    r.x = *reinterpret_cast<uint32_t*>(&th);
    r.y = bf2w(le, lo);
    return r;
}

__device__ __forceinline__ void mma_bf16(float* c, const uint32_t* a, const uint32_t* b) {
    asm volatile(
        "mma.sync.aligned.m16n8k16.row.col.f32.bf16.bf16.f32 "
        "{%0,%1,%2,%3}, {%4,%5,%6,%7}, {%8,%9}, {%0,%1,%2,%3};"
        : "+f"(c[0]), "+f"(c[1]), "+f"(c[2]), "+f"(c[3])
        : "r"(a[0]), "r"(a[1]), "r"(a[2]), "r"(a[3]), "r"(b[0]), "r"(b[1]));
}

// ============================================================================
// small packing kernels
// ============================================================================
// batched pack: 8 [768,768] weights -> wqkvp (blk 0..5) / wop (blk 6,7)
__global__ void pack_w8(const float* __restrict__ w0, const float* __restrict__ w1,
                        const float* __restrict__ w2, const float* __restrict__ w3,
                        const float* __restrict__ w4, const float* __restrict__ w5,
                        const float* __restrict__ w6, const float* __restrict__ w7,
                        uint2* __restrict__ wqkvp, uint2* __restrict__ wop)
{
    const int blk = blockIdx.y;
    const float* w;
    switch (blk) {
        case 0: w = w0; break; case 1: w = w1; break; case 2: w = w2; break;
        case 3: w = w3; break; case 4: w = w4; break; case 5: w = w5; break;
        case 6: w = w6; break; default: w = w7; break;
    }
    int idx = blockIdx.x * 256 + threadIdx.x;
    if (idx >= 384 * 768) return;
    int p = idx / 768, n = idx % 768;
    uint2 v = packpair(w[(long long)(2 * p) * 768 + n],
                       w[(long long)(2 * p + 1) * 768 + n]);
    if (blk < 6) wqkvp[(long long)p * NQKV + blk * 768 + n] = v;
    else         wop[(long long)p * 1536 + (blk - 6) * 768 + n] = v;
}

__global__ void pack_f2(const float* __restrict__ src, uint2* __restrict__ dst,
                        int Nsrc, int dstN, int col_off, int total)
{
    int idx = blockIdx.x * 256 + threadIdx.x;
    if (idx >= total) return;
    int p = idx / Nsrc, n = idx % Nsrc;
    dst[(long long)p * dstN + col_off + n] =
        packpair(src[(long long)(2 * p) * Nsrc + n], src[(long long)(2 * p + 1) * Nsrc + n]);
}

__global__ void fold_bias(const float* b0, const float* b1, const float* b2,
                          const float* b3, const float* b4, const float* b5,
                          const float* rcb, const float* ccb, float* Bv)
{
    int idx = blockIdx.x * 256 + threadIdx.x;
    if (idx >= NQKV) return;
    int blk = idx / E_DIM, c = idx % E_DIM;
    const float* bs;
    switch (blk) {
        case 0: bs = b0; break; case 1: bs = b1; break; case 2: bs = b2; break;
        case 3: bs = b3; break; case 4: bs = b4; break; default: bs = b5; break;
    }
    float v = bs[c];
    if (blk == 0) v += rcb[c];
    if (blk == 3) v += ccb[c];
    Bv[idx] = v;
}

__global__ void split_f1(const float* __restrict__ src, uint2* __restrict__ dst, int totalPairs)
{
    int idx = blockIdx.x * 256 + threadIdx.x;
    if (idx >= totalPairs) return;
    float2 f = ((const float2*)src)[idx];
    dst[idx] = packpair(f.x, f.y);
}

// V F2 planes reconstructed from packed qkvp (hi+lo)
__global__ void split_v(const uint2* __restrict__ qkvp, uint2* __restrict__ v)
{
    int idx = blockIdx.x * 256 + threadIdx.x;
    const int total = B_SZ * 1024 * 1536;
    if (idx >= total) return;
    int b = idx / (1024 * 1536);
    int r = idx % (1024 * 1536);
    int p = r / 1536, n = r % 1536;
    int col = (n < 768) ? (1536 + n) : (3072 + n);
    int cp = col >> 1, half = col & 1;
    const uint2 w0 = qkvp[(size_t)(b * 2048 + 2 * p) * 2304 + cp];
    const uint2 w1 = qkvp[(size_t)(b * 2048 + 2 * p + 1) * 2304 + cp];
    __nv_bfloat162 h0 = *(const __nv_bfloat162*)&w0.x;
    __nv_bfloat162 l0 = *(const __nv_bfloat162*)&w0.y;
    __nv_bfloat162 h1 = *(const __nv_bfloat162*)&w1.x;
    __nv_bfloat162 l1 = *(const __nv_bfloat162*)&w1.y;
    float e = half ? (__bfloat162float(h0.y) + __bfloat162float(l0.y))
                   : (__bfloat162float(h0.x) + __bfloat162float(l0.x));
    float o = half ? (__bfloat162float(h1.y) + __bfloat162float(l1.y))
                   : (__bfloat162float(h1.x) + __bfloat162float(l1.x));
    v[idx] = packpair(e, o);
}

// ============================================================================
// NN GEMM, bf16x3 (unchanged)
// ============================================================================
__global__ void __launch_bounds__(128) gemm_bf3_nn(
    const uint2* __restrict__ A, const uint2* __restrict__ B,
    float* __restrict__ Cf, uint2* __restrict__ Cp,
    const float* __restrict__ bias,
    int K, int lda2, int ldbN, int ldc, int ldc2,
    long long sA2, long long sBb, long long sBh,
    long long sCpb, long long sCph, int nh)
{
    __shared__ uint2 As[128 * SP_A];
    __shared__ uint2 Bs[16 * SP_BN];
    const int tid = threadIdx.x;
    const int wid = tid >> 5, lane = tid & 31;
    const int gid = lane >> 2, tig = lane & 3;
    const int wm = wid >> 1, wn = wid & 1;
    const int z = blockIdx.z, b = z / nh, h = z % nh;
    const uint2* Ap = A + (long long)z * sA2;
    const uint2* Bp = B + (long long)b * sBb + (long long)h * sBh;
    const int row0 = blockIdx.y * 128, col0 = blockIdx.x * 64;

    uint4 pa[8], pbuf[4];
    #pragma unroll
    for (int it = 0; it < 8; it++) {
        int lin = it * 128 + tid; int m = lin >> 3, p4 = (lin & 7) << 1;
        pa[it] = *(const uint4*)(Ap + (long long)(row0 + m) * lda2 + p4);
    }
    #pragma unroll
    for (int it = 0; it < 4; it++) {
        int lin = it * 128 + tid; int p = lin >> 5, n2 = (lin & 31) << 1;
        pbuf[it] = *(const uint4*)(Bp + (long long)p * ldbN + col0 + n2);
    }

    float acc[4][4][4] = {};

    for (int k0 = 0; k0 < K; k0 += 32) {
        #pragma unroll
        for (int it = 0; it < 8; it++) {
            int lin = it * 128 + tid; int m = lin >> 3, p4 = (lin & 7) << 1;
            *(uint4*)&As[m * SP_A + p4] = pa[it];
        }
        #pragma unroll
        for (int it = 0; it < 4; it++) {
            int lin = it * 128 + tid; int p = lin >> 5, n2 = (lin & 31) << 1;
            *(uint4*)&Bs[p * SP_BN + n2] = pbuf[it];
        }
        __syncthreads();
        if (k0 + 32 < K) {
            int k02 = (k0 + 32) >> 1;
            #pragma unroll
            for (int it = 0; it < 8; it++) {
                int lin = it * 128 + tid; int m = lin >> 3, p4 = (lin & 7) << 1;
                pa[it] = *(const uint4*)(Ap + (long long)(row0 + m) * lda2 + k02 + p4);
            }
            #pragma unroll
            for (int it = 0; it < 4; it++) {
                int lin = it * 128 + tid; int p = lin >> 5, n2 = (lin & 31) << 1;
                pbuf[it] = *(const uint4*)(Bp + (long long)(k02 + p) * ldbN + col0 + n2);
            }
        }
        #pragma unroll
        for (int pb2 = 0; pb2 < 16; pb2 += 8) {
            uint32_t bh[4][2], bl[4][2];
            #pragma unroll
            for (int j = 0; j < 4; j++) {
                int n = wn * 32 + j * 8 + gid;
                uint2 e0 = Bs[(pb2 + tig) * SP_BN + n];
                uint2 e1 = Bs[(pb2 + tig + 4) * SP_BN + n];
                bh[j][0] = e0.x; bl[j][0] = e0.y;
                bh[j][1] = e1.x; bl[j][1] = e1.y;
            }
            #pragma unroll
            for (int i = 0; i < 4; i++) {
                int mb = wm * 64 + i * 16 + gid;
                uint2 a0 = As[mb * SP_A + pb2 + tig];
                uint2 a1 = As[(mb + 8) * SP_A + pb2 + tig];
                uint2 a2 = As[mb * SP_A + pb2 + tig + 4];
                uint2 a3 = As[(mb + 8) * SP_A + pb2 + tig + 4];
                uint32_t ah[4] = {a0.x, a1.x, a2.x, a3.x};
                uint32_t al[4] = {a0.y, a1.y, a2.y, a3.y};
                #pragma unroll
                for (int j = 0; j < 4; j++) {
                    mma_bf16(acc[i][j], ah, bh[j]);
                    mma_bf16(acc[i][j], al, bh[j]);
                    mma_bf16(acc[i][j], ah, bl[j]);
                }
            }
        }
        __syncthreads();
    }

    uint2* Cpb = Cp ? (Cp + (long long)b * sCpb + (long long)h * sCph) : nullptr;
    #pragma unroll
    for (int i = 0; i < 4; i++) {
        int r0 = row0 + wm * 64 + i * 16 + gid;
        #pragma unroll
        for (int j = 0; j < 4; j++) {
            int c = col0 + wn * 32 + j * 8 + tig * 2;
            float b0 = 0.f, b1 = 0.f;
            if (bias) { b0 = bias[c]; b1 = bias[c + 1]; }
            float v00 = acc[i][j][0] + b0, v01 = acc[i][j][1] + b1;
            float v10 = acc[i][j][2] + b0, v11 = acc[i][j][3] + b1;
            if (Cf) {
                float2 t0 = {v00, v01}, t1 = {v10, v11};
                *(float2*)(Cf + (long long)r0 * ldc + c) = t0;
                *(float2*)(Cf + (long long)(r0 + 8) * ldc + c) = t1;
            }
            if (Cpb) {
                Cpb[(long long)r0 * ldc2 + (c >> 1)] = packpair(v00, v01);
                Cpb[(long long)(r0 + 8) * ldc2 + (c >> 1)] = packpair(v10, v11);
            }
        }
    }
}

// ============================================================================
// NT scores GEMM (cultural branch only; unchanged)
// ============================================================================
__global__ void __launch_bounds__(128) gemm_bf3_nt_scores(
    const uint2* __restrict__ Qb, const uint2* __restrict__ Kb,
    float* __restrict__ Sc,
    const float* __restrict__ am, const float* __restrict__ cm,
    float scale, int hd, int nh, int lda2)
{
    __shared__ uint2 As[128 * SP_A];
    __shared__ uint2 Bs[64 * SP_BT];
    const int tid = threadIdx.x;
    const int wid = tid >> 5, lane = tid & 31;
    const int gid = lane >> 2, tig = lane & 3;
    const int wm = wid >> 1, wn = wid & 1;
    const int z = blockIdx.z, b = z / nh, h = z % nh;
    const int hp = hd >> 1;
    const uint2* Qp = Qb + (long long)b * S_LEN * lda2 + h * hp;
    const uint2* Kp = Kb + (long long)b * S_LEN * lda2 + h * hp;
    float* Cpt = Sc + (long long)z * S_LEN * S_LEN;
    const int row0 = blockIdx.y * 128, col0 = blockIdx.x * 64;

    uint4 pa[8], pbuf[4];
    #pragma unroll
    for (int it = 0; it < 8; it++) {
        int lin = it * 128 + tid; int m = lin >> 3, p4 = (lin & 7) << 1;
        pa[it] = *(const uint4*)(Qp + (long long)(row0 + m) * lda2 + p4);
    }
    #pragma unroll
    for (int it = 0; it < 4; it++) {
        int lin = it * 128 + tid; int n = lin >> 3, p4 = (lin & 7) << 1;
        pbuf[it] = *(const uint4*)(Kp + (long long)(col0 + n) * lda2 + p4);
    }

    float acc[4][4][4] = {};

    for (int k0 = 0; k0 < hd; k0 += 32) {
        #pragma unroll
        for (int it = 0; it < 8; it++) {
            int lin = it * 128 + tid; int m = lin >> 3, p4 = (lin & 7) << 1;
            *(uint4*)&As[m * SP_A + p4] = pa[it];
        }
        #pragma unroll
        for (int it = 0; it < 4; it++) {
            int lin = it * 128 + tid; int n = lin >> 3, p4 = (lin & 7) << 1;
            *(uint4*)&Bs[n * SP_BT + p4] = pbuf[it];
        }
        __syncthreads();
        if (k0 + 32 < hd) {
            int k02 = (k0 + 32) >> 1;
            #pragma unroll
            for (int it = 0; it < 8; it++) {
                int lin = it * 128 + tid; int m = lin >> 3, p4 = (lin & 7) << 1;
                pa[it] = *(const uint4*)(Qp + (long long)(row0 + m) * lda2 + k02 + p4);
            }
            #pragma unroll
            for (int it = 0; it < 4; it++) {
                int lin = it * 128 + tid; int n = lin >> 3, p4 = (lin & 7) << 1;
                pbuf[it] = *(const uint4*)(Kp + (long long)(col0 + n) * lda2 + k02 + p4);
            }
        }
        #pragma unroll
        for (int pb2 = 0; pb2 < 16; pb2 += 8) {
            uint32_t bh[4][2], bl[4][2];
            #pragma unroll
            for (int j = 0; j < 4; j++) {
                int n = wn * 32 + j * 8 + gid;
                uint2 e0 = Bs[n * SP_BT + pb2 + tig];
                uint2 e1 = Bs[n * SP_BT + pb2 + tig + 4];
                bh[j][0] = e0.x; bl[j][0] = e0.y;
                bh[j][1] = e1.x; bl[j][1] = e1.y;
            }
            #pragma unroll
            for (int i = 0; i < 4; i++) {
                int mb = wm * 64 + i * 16 + gid;
                uint2 a0 = As[mb * SP_A + pb2 + tig];
                uint2 a1 = As[(mb + 8) * SP_A + pb2 + tig];
                uint2 a2 = As[mb * SP_A + pb2 + tig + 4];
                uint2 a3 = As[(mb + 8) * SP_A + pb2 + tig + 4];
                uint32_t ah[4] = {a0.x, a1.x, a2.x, a3.x};
                uint32_t al[4] = {a0.y, a1.y, a2.y, a3.y};
                #pragma unroll
                for (int j = 0; j < 4; j++) {
                    mma_bf16(acc[i][j], ah, bh[j]);
                    mma_bf16(acc[i][j], al, bh[j]);
                    mma_bf16(acc[i][j], ah, bl[j]);
                }
            }
        }
        __syncthreads();
    }

    #pragma unroll
    for (int i = 0; i < 4; i++) {
        int t0 = row0 + wm * 64 + i * 16 + gid;
        #pragma unroll
        for (int j = 0; j < 4; j++) {
            int s = col0 + wn * 32 + j * 8 + tig * 2;
            float m0 = am[b * S_LEN + s], m1 = am[b * S_LEN + s + 1];
            float n0 = m0, n1 = m1;
            if (cm) {
                const float* cmr0 = cm + ((long long)b * S_LEN + t0) * S_LEN;
                const float* cmr1 = cmr0 + 8LL * S_LEN;
                m0 += cmr0[s]; m1 += cmr0[s + 1];
                n0 += cmr1[s]; n1 += cmr1[s + 1];
            }
            float2 v0 = { acc[i][j][0] * scale + m0, acc[i][j][1] * scale + m1 };
            float2 v1 = { acc[i][j][2] * scale + n0, acc[i][j][3] * scale + n1 };
            *(float2*)(Cpt + (long long)t0 * S_LEN + s) = v0;
            *(float2*)(Cpt + (long long)(t0 + 8) * S_LEN + s) = v1;
        }
    }
}

// ============================================================================
// Flash-fused regular branch v3: 8 warps in 4m x 2n layout; each warp runs an
// independent online softmax over its kv-half; exact split-KV merge via smem
// (reusing the K double-buffer region) at the end.
// ============================================================================
__global__ void __launch_bounds__(256, 1) flash_reg(
    const uint2* __restrict__ qkvp, const uint2* __restrict__ vf2,
    const float* __restrict__ am, uint2* __restrict__ arp, float scale)
{
    extern __shared__ uint2 sm[];
    uint2* Qs = sm;
    uint2* Ks = Qs + FQ_SZ;
    uint2* Vs = Ks + 2 * FK_SZ;
    float* ams = (float*)(Vs + 2 * FV_SZ);

    const int tid = threadIdx.x, wid = tid >> 5, lane = tid & 31;
    const int gid = lane >> 2, tig = lane & 3;
    const int wm = wid >> 1, wn = wid & 1;
    const int qt = blockIdx.x;
    const int z = blockIdx.y, b = z / NH_R, h = z % NH_R;

    const long long qrow0 = (long long)b * S_LEN + qt * 128;
    const uint2* Qg = qkvp + qrow0 * 2304 + h * 64;
    const uint2* Kg = qkvp + (long long)b * S_LEN * 2304 + 384 + h * 64;
    const uint2* Vg = vf2 + (long long)b * 1024 * 1536 + h * 128;
    const float* amb = am + (long long)b * S_LEN;

    #pragma unroll
    for (int it = 0; it < 16; it++) {
        int lin = it * 256 + tid;
        int r = lin >> 5, p2 = (lin & 31) << 1;
        CP16(smem_u32(&Qs[r * FQ_S + p2]), Qg + (long long)r * 2304 + p2);
    }
    #pragma unroll
    for (int it = 0; it < 8; it++) {
        int lin = it * 256 + tid;
        int r = lin >> 5, p2 = (lin & 31) << 1;
        CP16(smem_u32(&Ks[r * FK_S + p2]), Kg + (long long)r * 2304 + p2);
    }
    #pragma unroll
    for (int it = 0; it < 8; it++) {
        int lin = it * 256 + tid;
        int p = lin >> 6, n2 = (lin & 63) << 1;
        CP16(smem_u32(&Vs[p * FV_S + n2]), Vg + (long long)p * 1536 + n2);
    }
    if (tid < 16) CP16(smem_u32(&ams[tid * 4]), amb + tid * 4);
    CP_COMMIT();

    float oac[2][16][4] = {};
    float mst[4] = {-1e30f, -1e30f, -1e30f, -1e30f};
    float lst[4] = {0.f, 0.f, 0.f, 0.f};
    const int mrow = wm * 32;

    CP_WAIT0();
    __syncthreads();

    for (int kt = 0; kt < 32; kt++) {
        if (kt + 1 < 32) {
            int nb = (kt + 1) & 1;
            uint2* Kd = Ks + nb * FK_SZ;
            uint2* Vd = Vs + nb * FV_SZ;
            #pragma unroll
            for (int it = 0; it < 8; it++) {
                int lin = it * 256 + tid;
                int r = lin >> 5, p2 = (lin & 31) << 1;
                CP16(smem_u32(&Kd[r * FK_S + p2]),
                     Kg + (long long)((kt + 1) * 64 + r) * 2304 + p2);
            }
            #pragma unroll
            for (int it = 0; it < 8; it++) {
                int lin = it * 256 + tid;
                int p = lin >> 6, n2 = (lin & 63) << 1;
                CP16(smem_u32(&Vd[p * FV_S + n2]),
                     Vg + (long long)((kt + 1) * 32 + p) * 1536 + n2);
            }
            if (tid < 16)
                CP16(smem_u32(&ams[nb * 64 + tid * 4]), amb + (kt + 1) * 64 + tid * 4);
            CP_COMMIT();
        }

        const uint2* Kb = Ks + (kt & 1) * FK_SZ;
        const uint2* Vb = Vs + (kt & 1) * FV_SZ;
        const float* amc = ams + (kt & 1) * 64;

        // ---- S = Q @ K^T over this warp's 32 rows x 32 kv-cols ----
        float sac[2][4][4] = {};
        #pragma unroll
        for (int t = 0; t < 8; t++) {
            uint32_t ah[2][4], al[2][4];
            #pragma unroll
            for (int i = 0; i < 2; i++) {
                int mr = mrow + i * 16 + gid;
                uint2 a0 = Qs[mr * FQ_S + 8 * t + tig];
                uint2 a1 = Qs[(mr + 8) * FQ_S + 8 * t + tig];
                uint2 a2 = Qs[mr * FQ_S + 8 * t + tig + 4];
                uint2 a3 = Qs[(mr + 8) * FQ_S + 8 * t + tig + 4];
                ah[i][0] = a0.x; ah[i][1] = a1.x; ah[i][2] = a2.x; ah[i][3] = a3.x;
                al[i][0] = a0.y; al[i][1] = a1.y; al[i][2] = a2.y; al[i][3] = a3.y;
            }
            #pragma unroll
            for (int j = 0; j < 4; j++) {
                int n = wn * 32 + j * 8 + gid;
                uint2 e0 = Kb[n * FK_S + 8 * t + tig];
                uint2 e1 = Kb[n * FK_S + 8 * t + tig + 4];
                uint32_t bh[2] = {e0.x, e1.x};
                uint32_t bl[2] = {e0.y, e1.y};
                #pragma unroll
                for (int i = 0; i < 2; i++) {
                    mma_bf16(sac[i][j], ah[i], bh);
                    mma_bf16(sac[i][j], al[i], bh);
                    mma_bf16(sac[i][j], ah[i], bl);
                }
            }
        }

        // ---- mask + per-half online softmax ----
        uint32_t ph[2][2][4], pl[2][2][4];
        #pragma unroll
        for (int i = 0; i < 2; i++) {
            float mx0 = -1e30f, mx1 = -1e30f;
            #pragma unroll
            for (int j = 0; j < 4; j++) {
                float a0 = amc[wn * 32 + 8 * j + 2 * tig];
                float a1 = amc[wn * 32 + 8 * j + 2 * tig + 1];
                sac[i][j][0] = sac[i][j][0] * scale + a0;
                sac[i][j][1] = sac[i][j][1] * scale + a1;
                sac[i][j][2] = sac[i][j][2] * scale + a0;
                sac[i][j][3] = sac[i][j][3] * scale + a1;
                mx0 = fmaxf(mx0, fmaxf(sac[i][j][0], sac[i][j][1]));
                mx1 = fmaxf(mx1, fmaxf(sac[i][j][2], sac[i][j][3]));
            }
            mx0 = fmaxf(mx0, __shfl_xor_sync(0xffffffffu, mx0, 1));
            mx0 = fmaxf(mx0, __shfl_xor_sync(0xffffffffu, mx0, 2));
            mx1 = fmaxf(mx1, __shfl_xor_sync(0xffffffffu, mx1, 1));
            mx1 = fmaxf(mx1, __shfl_xor_sync(0xffffffffu, mx1, 2));
            float mn0 = fmaxf(mst[2 * i], mx0), mn1 = fmaxf(mst[2 * i + 1], mx1);
            float sc0 = __expf(mst[2 * i] - mn0), sc1 = __expf(mst[2 * i + 1] - mn1);
            float ps0 = 0.f, ps1 = 0.f;
            #pragma unroll
            for (int j = 0; j < 4; j++) {
                sac[i][j][0] = __expf(sac[i][j][0] - mn0);
                sac[i][j][1] = __expf(sac[i][j][1] - mn0);
                sac[i][j][2] = __expf(sac[i][j][2] - mn1);
                sac[i][j][3] = __expf(sac[i][j][3] - mn1);
                ps0 += sac[i][j][0] + sac[i][j][1];
                ps1 += sac[i][j][2] + sac[i][j][3];
            }
            ps0 += __shfl_xor_sync(0xffffffffu, ps0, 1);
            ps0 += __shfl_xor_sync(0xffffffffu, ps0, 2);
            ps1 += __shfl_xor_sync(0xffffffffu, ps1, 1);
            ps1 += __shfl_xor_sync(0xffffffffu, ps1, 2);
            lst[2 * i]     = lst[2 * i] * sc0 + ps0;
            lst[2 * i + 1] = lst[2 * i + 1] * sc1 + ps1;
            mst[2 * i] = mn0; mst[2 * i + 1] = mn1;

            #pragma unroll
            for (int n = 0; n < 16; n++) {
                oac[i][n][0] *= sc0; oac[i][n][1] *= sc0;
                oac[i][n][2] *= sc1; oac[i][n][3] *= sc1;
            }

            #pragma unroll
            for (int t = 0; t < 2; t++) {
                uint2 w0 = packpair(sac[i][2 * t][0], sac[i][2 * t][1]);
                uint2 w1 = packpair(sac[i][2 * t][2], sac[i][2 * t][3]);
                uint2 w2 = packpair(sac[i][2 * t + 1][0], sac[i][2 * t + 1][1]);
                uint2 w3 = packpair(sac[i][2 * t + 1][2], sac[i][2 * t + 1][3]);
                ph[i][t][0] = w0.x; pl[i][t][0] = w0.y;
                ph[i][t][1] = w1.x; pl[i][t][1] = w1.y;
                ph[i][t][2] = w2.x; pl[i][t][2] = w2.y;
                ph[i][t][3] = w3.x; pl[i][t][3] = w3.y;
            }
        }

        // ---- O += P @ V over this warp's kv-half ----
        #pragma unroll
        for (int t = 0; t < 2; t++) {
            int pt = 2 * wn + t;
            #pragma unroll
            for (int n = 0; n < 16; n++) {
                uint2 e0 = Vb[(8 * pt + tig) * FV_S + 8 * n + gid];
                uint2 e1 = Vb[(8 * pt + tig + 4) * FV_S + 8 * n + gid];
                uint32_t bh[2] = {e0.x, e1.x};
                uint32_t bl[2] = {e0.y, e1.y};
                #pragma unroll
                for (int i = 0; i < 2; i++) {
                    mma_bf16(oac[i][n], ph[i][t], bh);
                    mma_bf16(oac[i][n], pl[i][t], bh);
                    mma_bf16(oac[i][n], ph[i][t], bl);
                }
            }
        }

        if (kt + 1 < 32) {
            CP_WAIT0();
            __syncthreads();
        }
    }

    // ---- exact split-KV merge across wn pairs (reuse K buffer smem) ----
    __syncthreads();
    float* mrg = (float*)Ks;                 // 4 x 4352 floats = 69632 B
    const int mbase = wm * 4352 + lane * 136;
    if (wn == 1) {
        #pragma unroll
        for (int i = 0; i < 2; i++)
            #pragma unroll
            for (int n = 0; n < 16; n++)
                #pragma unroll
                for (int c = 0; c < 4; c++)
                    mrg[mbase + (i * 16 + n) * 4 + c] = oac[i][n][c];
        #pragma unroll
        for (int s = 0; s < 4; s++) {
            mrg[mbase + 128 + s] = mst[s];
            mrg[mbase + 132 + s] = lst[s];
        }
    }
    __syncthreads();
    if (wn == 0) {
        float scS[4], scO[4], lm[4];
        #pragma unroll
        for (int s = 0; s < 4; s++) {
            float pm = mrg[mbase + 128 + s];
            float pv = mrg[mbase + 132 + s];
            float mm = fmaxf(mst[s], pm);
            scS[s] = __expf(mst[s] - mm);
            scO[s] = __expf(pm - mm);
            lm[s] = lst[s] * scS[s] + pv * scO[s];
        }
        #pragma unroll
        for (int i = 0; i < 2; i++) {
            float rl0 = 1.f / lm[2 * i], rl1 = 1.f / lm[2 * i + 1];
            long long r0 = qrow0 + mrow + i * 16 + gid;
            uint2* op0 = arp + r0 * 384 + h * 64;
            uint2* op1 = op0 + 8LL * 384;
            #pragma unroll
            for (int n = 0; n < 16; n++) {
                const float* po = &mrg[mbase + (i * 16 + n) * 4];
                float o0 = oac[i][n][0] * scS[2 * i]     + po[0] * scO[2 * i];
                float o1 = oac[i][n][1] * scS[2 * i]     + po[1] * scO[2 * i];
                float o2 = oac[i][n][2] * scS[2 * i + 1] + po[2] * scO[2 * i + 1];
                float o3 = oac[i][n][3] * scS[2 * i + 1] + po[3] * scO[2 * i + 1];
                op0[4 * n + tig] = packpair(o0 * rl0, o1 * rl0);
                op1[4 * n + tig] = packpair(o2 * rl1, o3 * rl1);
            }
        }
    }
}

// ============================================================================
// row softmax + pack to F1 (cultural branch)
// ============================================================================
__global__ void __launch_bounds__(256) softmax_pack(const float* __restrict__ in,
                                                    uint2* __restrict__ out)
{
    const long long row = blockIdx.x;
    const float2* r = (const float2*)(in + row * S_LEN);
    uint2* o = out + row * (S_LEN / 2);
    const int tid = threadIdx.x;
    __shared__ float red[256];

    float2 v[4];
    float mx = -1e30f;
    #pragma unroll
    for (int i = 0; i < 4; i++) {
        v[i] = r[tid + i * 256];
        mx = fmaxf(mx, fmaxf(v[i].x, v[i].y));
    }
    red[tid] = mx; __syncthreads();
    for (int s = 128; s > 0; s >>= 1) {
        if (tid < s) red[tid] = fmaxf(red[tid], red[tid + s]);
        __syncthreads();
    }
    mx = red[0];
    __syncthreads();

    float sum = 0.f;
    #pragma unroll
    for (int i = 0; i < 4; i++) {
        v[i].x = __expf(v[i].x - mx);
        v[i].y = __expf(v[i].y - mx);
        sum += v[i].x + v[i].y;
    }
    red[tid] = sum; __syncthreads();
    for (int s = 128; s > 0; s >>= 1) {
        if (tid < s) red[tid] += red[tid + s];
        __syncthreads();
    }
    const float inv = 1.0f / red[0];
    #pragma unroll
    for (int i = 0; i < 4; i++)
        o[tid + i * 256] = packpair(v[i].x * inv, v[i].y * inv);
}

// ============================================================================
template <typename T>
static T* symaddr(const void* s) {
    void* p = nullptr;
    cudaGetSymbolAddress(&p, s);
    return (T*)p;
}

extern "C" void kernel_launch(void* const* d_in, const int* in_sizes, int n_in,
                              void* d_out, int out_size)
{
    const float* x    = (const float*)d_in[0];
    const float* cm   = (const float*)d_in[1];
    const float* am   = (const float*)d_in[2];
    const float* rq_w = (const float*)d_in[3];
    const float* rk_w = (const float*)d_in[4];
    const float* rv_w = (const float*)d_in[5];
    const float* ro_w = (const float*)d_in[6];
    const float* cq_w = (const float*)d_in[7];
    const float* ck_w = (const float*)d_in[8];
    const float* cv_w = (const float*)d_in[9];
    const float* co_w = (const float*)d_in[10];
    const float* rq_b = (const float*)d_in[11];
    const float* rk_b = (const float*)d_in[12];
    const float* rv_b = (const float*)d_in[13];
    const float* ro_b = (const float*)d_in[14];
    const float* cq_b = (const float*)d_in[15];
    const float* ck_b = (const float*)d_in[16];
    const float* cv_b = (const float*)d_in[17];
    const float* co_b = (const float*)d_in[18];
    const float* r_cb = (const float*)d_in[19];
    const float* c_cb = (const float*)d_in[20];
    const float* out_w = (const float*)d_in[21];
    const float* out_b = (const float*)d_in[22];
    float* out = (float*)d_out;

    uint2* xp    = symaddr<uint2>(g_xp);
    uint2* wqkvp = symaddr<uint2>(g_wqkvp);
    float* bqkv  = symaddr<float>(g_bqkv);
    uint2* qkvp  = symaddr<uint2>(g_qkvp);
    uint2* vf2   = symaddr<uint2>(g_vf2);
    float* sc    = symaddr<float>(g_sc);
    uint2* scp   = symaddr<uint2>(g_scp);
    uint2* arp   = symaddr<uint2>(g_arp);
    uint2* acp   = symaddr<uint2>(g_acp);
    uint2* wop   = symaddr<uint2>(g_wop);
    uint2* outwp = symaddr<uint2>(g_outwp);
    uint2* catp  = symaddr<uint2>(g_catp);

    cudaFuncSetAttribute(flash_reg, cudaFuncAttributeMaxDynamicSharedMemorySize, FLASH_SMEM);

    cudaStream_t s2;
    cudaStreamCreateWithFlags(&s2, cudaStreamNonBlocking);
    cudaEvent_t evFork, evV, evJoin;
    cudaEventCreateWithFlags(&evFork, cudaEventDisableTiming);
    cudaEventCreateWithFlags(&evV, cudaEventDisableTiming);
    cudaEventCreateWithFlags(&evJoin, cudaEventDisableTiming);

    dim3 blk(128);

    // ---- pack weights (batched) + biases + split x ----
    {
        dim3 g8((384 * 768 + 255) / 256, 8);
        pack_w8<<<g8, 256>>>(rq_w, rk_w, rv_w, cq_w, ck_w, cv_w, ro_w, co_w,
                             wqkvp, wop);
        const int toto = 768 * 768;
        pack_f2<<<(toto + 255) / 256, 256>>>(out_w, outwp, 768, 768, 0, toto);
        fold_bias<<<(NQKV + 255) / 256, 256>>>(rq_b, rk_b, rv_b, cq_b, ck_b, cv_b,
                                               r_cb, c_cb, bqkv);
        const int tp = M_TOT * 384;
        split_f1<<<(tp + 255) / 256, 256>>>(x, xp, tp);
    }

    // ---- fused QKV projection (packed output only) ----
    dim3 gq(NQKV / 64, M_TOT / 128, 1);
    gemm_bf3_nn<<<gq, blk>>>(xp, wqkvp, nullptr, qkvp, bqkv,
                             E_DIM, 384, NQKV, 0, 2304,
                             0, 0, 0, 0, 0, 1);

    // ---- fork: cultural scores+softmax need only qkvp ----
    cudaEventRecord(evFork, 0);
    cudaStreamWaitEvent(s2, evFork, 0);
    {
        const float scale_c = 1.0f / sqrtf((float)HD_C);
        dim3 gsc(S_LEN / 64, S_LEN / 128, B_SZ * NH_C);
        gemm_bf3_nt_scores<<<gsc, blk, 0, s2>>>(qkvp + 1152, qkvp + 1536, sc,
                                                am, cm, scale_c, HD_C, NH_C, 2304);
        softmax_pack<<<B_SZ * NH_C * S_LEN, 256, 0, s2>>>(sc, scp);
    }

    // ---- main: split V, then flash + reg o-projection ----
    {
        const int tv = B_SZ * 1024 * 1536;
        split_v<<<(tv + 255) / 256, 256>>>(qkvp, vf2);
        cudaEventRecord(evV, 0);

        const float scale_r = 1.0f / sqrtf((float)HD_R);
        dim3 gf(16, B_SZ * NH_R);
        flash_reg<<<gf, 256, FLASH_SMEM>>>(qkvp, vf2, am, arp, scale_r);
        dim3 gp(E_DIM / 64, M_TOT / 128, 1);
        gemm_bf3_nn<<<gp, blk>>>(arp, wop, nullptr, catp, ro_b,
                                 E_DIM, 384, 1536, 0, 768,
                                 0, 0, 0, 0, 0, 1);
    }

    // ---- side: cultural PV (needs vf2) + o-projection ----
    {
        cudaStreamWaitEvent(s2, evV, 0);
        dim3 gac(HD_C / 64, S_LEN / 128, B_SZ * NH_C);
        gemm_bf3_nn<<<gac, blk, 0, s2>>>(scp, vf2 + 768, nullptr, acp, nullptr,
                                         S_LEN, 1024, 1536, 0, 384,
                                         (long long)S_LEN * 1024,
                                         (long long)1024 * 1536, HD_C,
                                         (long long)S_LEN * 384, HD_C / 2, NH_C);
        dim3 gp(E_DIM / 64, M_TOT / 128, 1);
        gemm_bf3_nn<<<gp, blk, 0, s2>>>(acp, wop + 768, nullptr, catp + 384, co_b,
                                        E_DIM, 384, 1536, 0, 768,
                                        0, 0, 0, 0, 0, 1);
    }

    // ---- join ----
    cudaEventRecord(evJoin, s2);
    cudaStreamWaitEvent(0, evJoin, 0);

    // ---- final: [M,2E] @ [2E,E] + out_b -> fp32 out ----
    dim3 gp(E_DIM / 64, M_TOT / 128, 1);
    gemm_bf3_nn<<<gp, blk>>>(catp, outwp, out, nullptr, out_b,
                             2 * E_DIM, 768, 768, 768, 0,
                             0, 0, 0, 0, 0, 1);
}

// round 12
// speedup vs baseline: 1.4388x; 1.0755x over previous
#include <cuda_runtime.h>
#include <cuda_bf16.h>
#include <math.h>
#include <stdint.h>

#define S_LEN 2048
#define E_DIM 768
#define B_SZ  2
#define NH_R  6
#define NH_C  2
#define HD_R  128
#define HD_C  384
#define M_TOT 4096
#define NQKV  4608

// smem strides (uint2 units); stride mod 16 == 4 -> conflict-free LDS.64 frags
#define SP_A  20
#define SP_BN 68
#define SP_BT 20

// flash smem geometry (uint2 units)
#define FQ_S 68
#define FK_S 68
#define FV_S 132
#define FQ_SZ (128*FQ_S)
#define FK_SZ (64*FK_S)
#define FV_SZ (32*FV_S)
#define FLASH_SMEM ((FQ_SZ + 2*FK_SZ + 2*FV_SZ)*8 + 2*64*4)   // 207,360 B

// -------- scratch ------------------------------------------------------------
__device__ uint2 g_xp[(size_t)M_TOT*384];
__device__ uint2 g_wqkvp[(size_t)384*NQKV];
__device__ float g_bqkv[NQKV];
__device__ uint2 g_qkvp[(size_t)M_TOT*2304];
__device__ uint2 g_vf2[(size_t)B_SZ*1024*1536];
__device__ float g_sc[(size_t)B_SZ*NH_C*S_LEN*S_LEN];
__device__ uint2 g_scp[(size_t)B_SZ*NH_C*S_LEN*1024];
__device__ uint2 g_catp2[(size_t)M_TOT*768];        // A' = [att_reg | att_cul] F1
// weight-fusion scratch
__device__ uint2 g_rowp[(size_t)768*384];           // ro_w F1
__device__ uint2 g_cowp[(size_t)768*384];           // co_w F1
__device__ uint2 g_outwp[(size_t)768*768];          // out_w F2
__device__ float g_w1f[(size_t)768*768];
__device__ float g_w2f[(size_t)768*768];
__device__ uint2 g_fwp[(size_t)768*768];            // [W1;W2] F2
__device__ float g_biasf[768];

// -------- helpers --------------------------------------------------------------
__device__ __forceinline__ uint32_t smem_u32(const void* p) {
    return (uint32_t)__cvta_generic_to_shared(p);
}
#define CP16(sa, ga) asm volatile("cp.async.cg.shared.global [%0], [%1], 16;" :: "r"(sa), "l"(ga))
#define CP_COMMIT()  asm volatile("cp.async.commit_group;" ::: "memory")
#define CP_WAIT0()   asm volatile("cp.async.wait_group 0;" ::: "memory")

__device__ __forceinline__ uint32_t bf2w(float a, float b) {
    __nv_bfloat162 t;
    t.x = __float2bfloat16(a); t.y = __float2bfloat16(b);
    return *reinterpret_cast<uint32_t*>(&t);
}
__device__ __forceinline__ uint2 packpair(float e, float o) {
    __nv_bfloat16 he = __float2bfloat16(e);
    __nv_bfloat16 ho = __float2bfloat16(o);
    float le = e - __bfloat162float(he);
    float lo = o - __bfloat162float(ho);
    uint2 r;
    __nv_bfloat162 th; th.x = he; th.y = ho;
    r.x = *reinterpret_cast<uint32_t*>(&th);
    r.y = bf2w(le, lo);
    return r;
}

__device__ __forceinline__ void mma_bf16(float* c, const uint32_t* a, const uint32_t* b) {
    asm volatile(
        "mma.sync.aligned.m16n8k16.row.col.f32.bf16.bf16.f32 "
        "{%0,%1,%2,%3}, {%4,%5,%6,%7}, {%8,%9}, {%0,%1,%2,%3};"
        : "+f"(c[0]), "+f"(c[1]), "+f"(c[2]), "+f"(c[3])
        : "r"(a[0]), "r"(a[1]), "r"(a[2]), "r"(a[3]), "r"(b[0]), "r"(b[1]));
}

// ============================================================================
// small packing kernels
// ============================================================================
__global__ void pack_w6(const float* __restrict__ w0, const float* __restrict__ w1,
                        const float* __restrict__ w2, const float* __restrict__ w3,
                        const float* __restrict__ w4, const float* __restrict__ w5,
                        uint2* __restrict__ wqkvp)
{
    const int blk = blockIdx.y;
    const float* w;
    switch (blk) {
        case 0: w = w0; break; case 1: w = w1; break; case 2: w = w2; break;
        case 3: w = w3; break; case 4: w = w4; break; default: w = w5; break;
    }
    int idx = blockIdx.x * 256 + threadIdx.x;
    if (idx >= 384 * 768) return;
    int p = idx / 768, n = idx % 768;
    wqkvp[(long long)p * NQKV + blk * 768 + n] =
        packpair(w[(long long)(2 * p) * 768 + n], w[(long long)(2 * p + 1) * 768 + n]);
}

__global__ void pack_f2(const float* __restrict__ src, uint2* __restrict__ dst,
                        int Nsrc, int dstN, int col_off, int total)
{
    int idx = blockIdx.x * 256 + threadIdx.x;
    if (idx >= total) return;
    int p = idx / Nsrc, n = idx % Nsrc;
    dst[(long long)p * dstN + col_off + n] =
        packpair(src[(long long)(2 * p) * Nsrc + n], src[(long long)(2 * p + 1) * Nsrc + n]);
}

__global__ void fold_bias(const float* b0, const float* b1, const float* b2,
                          const float* b3, const float* b4, const float* b5,
                          const float* rcb, const float* ccb, float* Bv)
{
    int idx = blockIdx.x * 256 + threadIdx.x;
    if (idx >= NQKV) return;
    int blk = idx / E_DIM, c = idx % E_DIM;
    const float* bs;
    switch (blk) {
        case 0: bs = b0; break; case 1: bs = b1; break; case 2: bs = b2; break;
        case 3: bs = b3; break; case 4: bs = b4; break; default: bs = b5; break;
    }
    float v = bs[c];
    if (blk == 0) v += rcb[c];
    if (blk == 3) v += ccb[c];
    Bv[idx] = v;
}

__global__ void split_f1(const float* __restrict__ src, uint2* __restrict__ dst, int totalPairs)
{
    int idx = blockIdx.x * 256 + threadIdx.x;
    if (idx >= totalPairs) return;
    float2 f = ((const float2*)src)[idx];
    dst[idx] = packpair(f.x, f.y);
}

// fused output bias: biasf[n] = ro_b.out_w_top[:,n] + co_b.out_w_bot[:,n] + out_b[n]
__global__ void fuse_bias(const float* __restrict__ ro_b, const float* __restrict__ co_b,
                          const float* __restrict__ out_w, const float* __restrict__ out_b,
                          float* __restrict__ biasf)
{
    int n = blockIdx.x * 256 + threadIdx.x;
    if (n >= 768) return;
    float s = out_b[n];
    for (int j = 0; j < 768; j++) {
        s += ro_b[j] * out_w[(long long)j * 768 + n];
        s += co_b[j] * out_w[(long long)(768 + j) * 768 + n];
    }
    biasf[n] = s;
}

// V F2 planes reconstructed from packed qkvp (hi+lo)
__global__ void split_v(const uint2* __restrict__ qkvp, uint2* __restrict__ v)
{
    int idx = blockIdx.x * 256 + threadIdx.x;
    const int total = B_SZ * 1024 * 1536;
    if (idx >= total) return;
    int b = idx / (1024 * 1536);
    int r = idx % (1024 * 1536);
    int p = r / 1536, n = r % 1536;
    int col = (n < 768) ? (1536 + n) : (3072 + n);
    int cp = col >> 1, half = col & 1;
    const uint2 w0 = qkvp[(size_t)(b * 2048 + 2 * p) * 2304 + cp];
    const uint2 w1 = qkvp[(size_t)(b * 2048 + 2 * p + 1) * 2304 + cp];
    __nv_bfloat162 h0 = *(const __nv_bfloat162*)&w0.x;
    __nv_bfloat162 l0 = *(const __nv_bfloat162*)&w0.y;
    __nv_bfloat162 h1 = *(const __nv_bfloat162*)&w1.x;
    __nv_bfloat162 l1 = *(const __nv_bfloat162*)&w1.y;
    float e = half ? (__bfloat162float(h0.y) + __bfloat162float(l0.y))
                   : (__bfloat162float(h0.x) + __bfloat162float(l0.x));
    float o = half ? (__bfloat162float(h1.y) + __bfloat162float(l1.y))
                   : (__bfloat162float(h1.x) + __bfloat162float(l1.x));
    v[idx] = packpair(e, o);
}

// ============================================================================
// NN GEMM, bf16x3 (unchanged)
// ============================================================================
__global__ void __launch_bounds__(128) gemm_bf3_nn(
    const uint2* __restrict__ A, const uint2* __restrict__ B,
    float* __restrict__ Cf, uint2* __restrict__ Cp,
    const float* __restrict__ bias,
    int K, int lda2, int ldbN, int ldc, int ldc2,
    long long sA2, long long sBb, long long sBh,
    long long sCpb, long long sCph, int nh)
{
    __shared__ uint2 As[128 * SP_A];
    __shared__ uint2 Bs[16 * SP_BN];
    const int tid = threadIdx.x;
    const int wid = tid >> 5, lane = tid & 31;
    const int gid = lane >> 2, tig = lane & 3;
    const int wm = wid >> 1, wn = wid & 1;
    const int z = blockIdx.z, b = z / nh, h = z % nh;
    const uint2* Ap = A + (long long)z * sA2;
    const uint2* Bp = B + (long long)b * sBb + (long long)h * sBh;
    const int row0 = blockIdx.y * 128, col0 = blockIdx.x * 64;

    uint4 pa[8], pbuf[4];
    #pragma unroll
    for (int it = 0; it < 8; it++) {
        int lin = it * 128 + tid; int m = lin >> 3, p4 = (lin & 7) << 1;
        pa[it] = *(const uint4*)(Ap + (long long)(row0 + m) * lda2 + p4);
    }
    #pragma unroll
    for (int it = 0; it < 4; it++) {
        int lin = it * 128 + tid; int p = lin >> 5, n2 = (lin & 31) << 1;
        pbuf[it] = *(const uint4*)(Bp + (long long)p * ldbN + col0 + n2);
    }

    float acc[4][4][4] = {};

    for (int k0 = 0; k0 < K; k0 += 32) {
        #pragma unroll
        for (int it = 0; it < 8; it++) {
            int lin = it * 128 + tid; int m = lin >> 3, p4 = (lin & 7) << 1;
            *(uint4*)&As[m * SP_A + p4] = pa[it];
        }
        #pragma unroll
        for (int it = 0; it < 4; it++) {
            int lin = it * 128 + tid; int p = lin >> 5, n2 = (lin & 31) << 1;
            *(uint4*)&Bs[p * SP_BN + n2] = pbuf[it];
        }
        __syncthreads();
        if (k0 + 32 < K) {
            int k02 = (k0 + 32) >> 1;
            #pragma unroll
            for (int it = 0; it < 8; it++) {
                int lin = it * 128 + tid; int m = lin >> 3, p4 = (lin & 7) << 1;
                pa[it] = *(const uint4*)(Ap + (long long)(row0 + m) * lda2 + k02 + p4);
            }
            #pragma unroll
            for (int it = 0; it < 4; it++) {
                int lin = it * 128 + tid; int p = lin >> 5, n2 = (lin & 31) << 1;
                pbuf[it] = *(const uint4*)(Bp + (long long)(k02 + p) * ldbN + col0 + n2);
            }
        }
        #pragma unroll
        for (int pb2 = 0; pb2 < 16; pb2 += 8) {
            uint32_t bh[4][2], bl[4][2];
            #pragma unroll
            for (int j = 0; j < 4; j++) {
                int n = wn * 32 + j * 8 + gid;
                uint2 e0 = Bs[(pb2 + tig) * SP_BN + n];
                uint2 e1 = Bs[(pb2 + tig + 4) * SP_BN + n];
                bh[j][0] = e0.x; bl[j][0] = e0.y;
                bh[j][1] = e1.x; bl[j][1] = e1.y;
            }
            #pragma unroll
            for (int i = 0; i < 4; i++) {
                int mb = wm * 64 + i * 16 + gid;
                uint2 a0 = As[mb * SP_A + pb2 + tig];
                uint2 a1 = As[(mb + 8) * SP_A + pb2 + tig];
                uint2 a2 = As[mb * SP_A + pb2 + tig + 4];
                uint2 a3 = As[(mb + 8) * SP_A + pb2 + tig + 4];
                uint32_t ah[4] = {a0.x, a1.x, a2.x, a3.x};
                uint32_t al[4] = {a0.y, a1.y, a2.y, a3.y};
                #pragma unroll
                for (int j = 0; j < 4; j++) {
                    mma_bf16(acc[i][j], ah, bh[j]);
                    mma_bf16(acc[i][j], al, bh[j]);
                    mma_bf16(acc[i][j], ah, bl[j]);
                }
            }
        }
        __syncthreads();
    }

    uint2* Cpb = Cp ? (Cp + (long long)b * sCpb + (long long)h * sCph) : nullptr;
    #pragma unroll
    for (int i = 0; i < 4; i++) {
        int r0 = row0 + wm * 64 + i * 16 + gid;
        #pragma unroll
        for (int j = 0; j < 4; j++) {
            int c = col0 + wn * 32 + j * 8 + tig * 2;
            float b0 = 0.f, b1 = 0.f;
            if (bias) { b0 = bias[c]; b1 = bias[c + 1]; }
            float v00 = acc[i][j][0] + b0, v01 = acc[i][j][1] + b1;
            float v10 = acc[i][j][2] + b0, v11 = acc[i][j][3] + b1;
            if (Cf) {
                float2 t0 = {v00, v01}, t1 = {v10, v11};
                *(float2*)(Cf + (long long)r0 * ldc + c) = t0;
                *(float2*)(Cf + (long long)(r0 + 8) * ldc + c) = t1;
            }
            if (Cpb) {
                Cpb[(long long)r0 * ldc2 + (c >> 1)] = packpair(v00, v01);
                Cpb[(long long)(r0 + 8) * ldc2 + (c >> 1)] = packpair(v10, v11);
            }
        }
    }
}

// ============================================================================
// NT scores GEMM (cultural branch only; unchanged)
// ============================================================================
__global__ void __launch_bounds__(128) gemm_bf3_nt_scores(
    const uint2* __restrict__ Qb, const uint2* __restrict__ Kb,
    float* __restrict__ Sc,
    const float* __restrict__ am, const float* __restrict__ cm,
    float scale, int hd, int nh, int lda2)
{
    __shared__ uint2 As[128 * SP_A];
    __shared__ uint2 Bs[64 * SP_BT];
    const int tid = threadIdx.x;
    const int wid = tid >> 5, lane = tid & 31;
    const int gid = lane >> 2, tig = lane & 3;
    const int wm = wid >> 1, wn = wid & 1;
    const int z = blockIdx.z, b = z / nh, h = z % nh;
    const int hp = hd >> 1;
    const uint2* Qp = Qb + (long long)b * S_LEN * lda2 + h * hp;
    const uint2* Kp = Kb + (long long)b * S_LEN * lda2 + h * hp;
    float* Cpt = Sc + (long long)z * S_LEN * S_LEN;
    const int row0 = blockIdx.y * 128, col0 = blockIdx.x * 64;

    uint4 pa[8], pbuf[4];
    #pragma unroll
    for (int it = 0; it < 8; it++) {
        int lin = it * 128 + tid; int m = lin >> 3, p4 = (lin & 7) << 1;
        pa[it] = *(const uint4*)(Qp + (long long)(row0 + m) * lda2 + p4);
    }
    #pragma unroll
    for (int it = 0; it < 4; it++) {
        int lin = it * 128 + tid; int n = lin >> 3, p4 = (lin & 7) << 1;
        pbuf[it] = *(const uint4*)(Kp + (long long)(col0 + n) * lda2 + p4);
    }

    float acc[4][4][4] = {};

    for (int k0 = 0; k0 < hd; k0 += 32) {
        #pragma unroll
        for (int it = 0; it < 8; it++) {
            int lin = it * 128 + tid; int m = lin >> 3, p4 = (lin & 7) << 1;
            *(uint4*)&As[m * SP_A + p4] = pa[it];
        }
        #pragma unroll
        for (int it = 0; it < 4; it++) {
            int lin = it * 128 + tid; int n = lin >> 3, p4 = (lin & 7) << 1;
            *(uint4*)&Bs[n * SP_BT + p4] = pbuf[it];
        }
        __syncthreads();
        if (k0 + 32 < hd) {
            int k02 = (k0 + 32) >> 1;
            #pragma unroll
            for (int it = 0; it < 8; it++) {
                int lin = it * 128 + tid; int m = lin >> 3, p4 = (lin & 7) << 1;
                pa[it] = *(const uint4*)(Qp + (long long)(row0 + m) * lda2 + k02 + p4);
            }
            #pragma unroll
            for (int it = 0; it < 4; it++) {
                int lin = it * 128 + tid; int n = lin >> 3, p4 = (lin & 7) << 1;
                pbuf[it] = *(const uint4*)(Kp + (long long)(col0 + n) * lda2 + k02 + p4);
            }
        }
        #pragma unroll
        for (int pb2 = 0; pb2 < 16; pb2 += 8) {
            uint32_t bh[4][2], bl[4][2];
            #pragma unroll
            for (int j = 0; j < 4; j++) {
                int n = wn * 32 + j * 8 + gid;
                uint2 e0 = Bs[n * SP_BT + pb2 + tig];
                uint2 e1 = Bs[n * SP_BT + pb2 + tig + 4];
                bh[j][0] = e0.x; bl[j][0] = e0.y;
                bh[j][1] = e1.x; bl[j][1] = e1.y;
            }
            #pragma unroll
            for (int i = 0; i < 4; i++) {
                int mb = wm * 64 + i * 16 + gid;
                uint2 a0 = As[mb * SP_A + pb2 + tig];
                uint2 a1 = As[(mb + 8) * SP_A + pb2 + tig];
                uint2 a2 = As[mb * SP_A + pb2 + tig + 4];
                uint2 a3 = As[(mb + 8) * SP_A + pb2 + tig + 4];
                uint32_t ah[4] = {a0.x, a1.x, a2.x, a3.x};
                uint32_t al[4] = {a0.y, a1.y, a2.y, a3.y};
                #pragma unroll
                for (int j = 0; j < 4; j++) {
                    mma_bf16(acc[i][j], ah, bh[j]);
                    mma_bf16(acc[i][j], al, bh[j]);
                    mma_bf16(acc[i][j], ah, bl[j]);
                }
            }
        }
        __syncthreads();
    }

    #pragma unroll
    for (int i = 0; i < 4; i++) {
        int t0 = row0 + wm * 64 + i * 16 + gid;
        #pragma unroll
        for (int j = 0; j < 4; j++) {
            int s = col0 + wn * 32 + j * 8 + tig * 2;
            float m0 = am[b * S_LEN + s], m1 = am[b * S_LEN + s + 1];
            float n0 = m0, n1 = m1;
            if (cm) {
                const float* cmr0 = cm + ((long long)b * S_LEN + t0) * S_LEN;
                const float* cmr1 = cmr0 + 8LL * S_LEN;
                m0 += cmr0[s]; m1 += cmr0[s + 1];
                n0 += cmr1[s]; n1 += cmr1[s + 1];
            }
            float2 v0 = { acc[i][j][0] * scale + m0, acc[i][j][1] * scale + m1 };
            float2 v1 = { acc[i][j][2] * scale + n0, acc[i][j][3] * scale + n1 };
            *(float2*)(Cpt + (long long)t0 * S_LEN + s) = v0;
            *(float2*)(Cpt + (long long)(t0 + 8) * S_LEN + s) = v1;
        }
    }
}

// ============================================================================
// Flash-fused regular branch (writes att_reg into catp2 cols 0-383)
// ============================================================================
__global__ void __launch_bounds__(256, 1) flash_reg(
    const uint2* __restrict__ qkvp, const uint2* __restrict__ vf2,
    const float* __restrict__ am, uint2* __restrict__ catp2, float scale)
{
    extern __shared__ uint2 sm[];
    uint2* Qs = sm;
    uint2* Ks = Qs + FQ_SZ;
    uint2* Vs = Ks + 2 * FK_SZ;
    float* ams = (float*)(Vs + 2 * FV_SZ);

    const int tid = threadIdx.x, wid = tid >> 5, lane = tid & 31;
    const int gid = lane >> 2, tig = lane & 3;
    const int wm = wid >> 1, wn = wid & 1;
    const int qt = blockIdx.x;
    const int z = blockIdx.y, b = z / NH_R, h = z % NH_R;

    const long long qrow0 = (long long)b * S_LEN + qt * 128;
    const uint2* Qg = qkvp + qrow0 * 2304 + h * 64;
    const uint2* Kg = qkvp + (long long)b * S_LEN * 2304 + 384 + h * 64;
    const uint2* Vg = vf2 + (long long)b * 1024 * 1536 + h * 128;
    const float* amb = am + (long long)b * S_LEN;

    #pragma unroll
    for (int it = 0; it < 16; it++) {
        int lin = it * 256 + tid;
        int r = lin >> 5, p2 = (lin & 31) << 1;
        CP16(smem_u32(&Qs[r * FQ_S + p2]), Qg + (long long)r * 2304 + p2);
    }
    #pragma unroll
    for (int it = 0; it < 8; it++) {
        int lin = it * 256 + tid;
        int r = lin >> 5, p2 = (lin & 31) << 1;
        CP16(smem_u32(&Ks[r * FK_S + p2]), Kg + (long long)r * 2304 + p2);
    }
    #pragma unroll
    for (int it = 0; it < 8; it++) {
        int lin = it * 256 + tid;
        int p = lin >> 6, n2 = (lin & 63) << 1;
        CP16(smem_u32(&Vs[p * FV_S + n2]), Vg + (long long)p * 1536 + n2);
    }
    if (tid < 16) CP16(smem_u32(&ams[tid * 4]), amb + tid * 4);
    CP_COMMIT();

    float oac[2][16][4] = {};
    float mst[4] = {-1e30f, -1e30f, -1e30f, -1e30f};
    float lst[4] = {0.f, 0.f, 0.f, 0.f};
    const int mrow = wm * 32;

    CP_WAIT0();
    __syncthreads();

    for (int kt = 0; kt < 32; kt++) {
        if (kt + 1 < 32) {
            int nb = (kt + 1) & 1;
            uint2* Kd = Ks + nb * FK_SZ;
            uint2* Vd = Vs + nb * FV_SZ;
            #pragma unroll
            for (int it = 0; it < 8; it++) {
                int lin = it * 256 + tid;
                int r = lin >> 5, p2 = (lin & 31) << 1;
                CP16(smem_u32(&Kd[r * FK_S + p2]),
                     Kg + (long long)((kt + 1) * 64 + r) * 2304 + p2);
            }
            #pragma unroll
            for (int it = 0; it < 8; it++) {
                int lin = it * 256 + tid;
                int p = lin >> 6, n2 = (lin & 63) << 1;
                CP16(smem_u32(&Vd[p * FV_S + n2]),
                     Vg + (long long)((kt + 1) * 32 + p) * 1536 + n2);
            }
            if (tid < 16)
                CP16(smem_u32(&ams[nb * 64 + tid * 4]), amb + (kt + 1) * 64 + tid * 4);
            CP_COMMIT();
        }

        const uint2* Kb = Ks + (kt & 1) * FK_SZ;
        const uint2* Vb = Vs + (kt & 1) * FV_SZ;
        const float* amc = ams + (kt & 1) * 64;

        float sac[2][4][4] = {};
        #pragma unroll
        for (int t = 0; t < 8; t++) {
            uint32_t ah[2][4], al[2][4];
            #pragma unroll
            for (int i = 0; i < 2; i++) {
                int mr = mrow + i * 16 + gid;
                uint2 a0 = Qs[mr * FQ_S + 8 * t + tig];
                uint2 a1 = Qs[(mr + 8) * FQ_S + 8 * t + tig];
                uint2 a2 = Qs[mr * FQ_S + 8 * t + tig + 4];
                uint2 a3 = Qs[(mr + 8) * FQ_S + 8 * t + tig + 4];
                ah[i][0] = a0.x; ah[i][1] = a1.x; ah[i][2] = a2.x; ah[i][3] = a3.x;
                al[i][0] = a0.y; al[i][1] = a1.y; al[i][2] = a2.y; al[i][3] = a3.y;
            }
            #pragma unroll
            for (int j = 0; j < 4; j++) {
                int n = wn * 32 + j * 8 + gid;
                uint2 e0 = Kb[n * FK_S + 8 * t + tig];
                uint2 e1 = Kb[n * FK_S + 8 * t + tig + 4];
                uint32_t bh[2] = {e0.x, e1.x};
                uint32_t bl[2] = {e0.y, e1.y};
                #pragma unroll
                for (int i = 0; i < 2; i++) {
                    mma_bf16(sac[i][j], ah[i], bh);
                    mma_bf16(sac[i][j], al[i], bh);
                    mma_bf16(sac[i][j], ah[i], bl);
                }
            }
        }

        uint32_t ph[2][2][4], pl[2][2][4];
        #pragma unroll
        for (int i = 0; i < 2; i++) {
            float mx0 = -1e30f, mx1 = -1e30f;
            #pragma unroll
            for (int j = 0; j < 4; j++) {
                float a0 = amc[wn * 32 + 8 * j + 2 * tig];
                float a1 = amc[wn * 32 + 8 * j + 2 * tig + 1];
                sac[i][j][0] = sac[i][j][0] * scale + a0;
                sac[i][j][1] = sac[i][j][1] * scale + a1;
                sac[i][j][2] = sac[i][j][2] * scale + a0;
                sac[i][j][3] = sac[i][j][3] * scale + a1;
                mx0 = fmaxf(mx0, fmaxf(sac[i][j][0], sac[i][j][1]));
                mx1 = fmaxf(mx1, fmaxf(sac[i][j][2], sac[i][j][3]));
            }
            mx0 = fmaxf(mx0, __shfl_xor_sync(0xffffffffu, mx0, 1));
            mx0 = fmaxf(mx0, __shfl_xor_sync(0xffffffffu, mx0, 2));
            mx1 = fmaxf(mx1, __shfl_xor_sync(0xffffffffu, mx1, 1));
            mx1 = fmaxf(mx1, __shfl_xor_sync(0xffffffffu, mx1, 2));
            float mn0 = fmaxf(mst[2 * i], mx0), mn1 = fmaxf(mst[2 * i + 1], mx1);
            float sc0 = __expf(mst[2 * i] - mn0), sc1 = __expf(mst[2 * i + 1] - mn1);
            float ps0 = 0.f, ps1 = 0.f;
            #pragma unroll
            for (int j = 0; j < 4; j++) {
                sac[i][j][0] = __expf(sac[i][j][0] - mn0);
                sac[i][j][1] = __expf(sac[i][j][1] - mn0);
                sac[i][j][2] = __expf(sac[i][j][2] - mn1);
                sac[i][j][3] = __expf(sac[i][j][3] - mn1);
                ps0 += sac[i][j][0] + sac[i][j][1];
                ps1 += sac[i][j][2] + sac[i][j][3];
            }
            ps0 += __shfl_xor_sync(0xffffffffu, ps0, 1);
            ps0 += __shfl_xor_sync(0xffffffffu, ps0, 2);
            ps1 += __shfl_xor_sync(0xffffffffu, ps1, 1);
            ps1 += __shfl_xor_sync(0xffffffffu, ps1, 2);
            lst[2 * i]     = lst[2 * i] * sc0 + ps0;
            lst[2 * i + 1] = lst[2 * i + 1] * sc1 + ps1;
            mst[2 * i] = mn0; mst[2 * i + 1] = mn1;

            #pragma unroll
            for (int n = 0; n < 16; n++) {
                oac[i][n][0] *= sc0; oac[i][n][1] *= sc0;
                oac[i][n][2] *= sc1; oac[i][n][3] *= sc1;
            }

            #pragma unroll
            for (int t = 0; t < 2; t++) {
                uint2 w0 = packpair(sac[i][2 * t][0], sac[i][2 * t][1]);
                uint2 w1 = packpair(sac[i][2 * t][2], sac[i][2 * t][3]);
                uint2 w2 = packpair(sac[i][2 * t + 1][0], sac[i][2 * t + 1][1]);
                uint2 w3 = packpair(sac[i][2 * t + 1][2], sac[i][2 * t + 1][3]);
                ph[i][t][0] = w0.x; pl[i][t][0] = w0.y;
                ph[i][t][1] = w1.x; pl[i][t][1] = w1.y;
                ph[i][t][2] = w2.x; pl[i][t][2] = w2.y;
                ph[i][t][3] = w3.x; pl[i][t][3] = w3.y;
            }
        }

        #pragma unroll
        for (int t = 0; t < 2; t++) {
            int pt = 2 * wn + t;
            #pragma unroll
            for (int n = 0; n < 16; n++) {
                uint2 e0 = Vb[(8 * pt + tig) * FV_S + 8 * n + gid];
                uint2 e1 = Vb[(8 * pt + tig + 4) * FV_S + 8 * n + gid];
                uint32_t bh[2] = {e0.x, e1.x};
                uint32_t bl[2] = {e0.y, e1.y};
                #pragma unroll
                for (int i = 0; i < 2; i++) {
                    mma_bf16(oac[i][n], ph[i][t], bh);
                    mma_bf16(oac[i][n], pl[i][t], bh);
                    mma_bf16(oac[i][n], ph[i][t], bl);
                }
            }
        }

        if (kt + 1 < 32) {
            CP_WAIT0();
            __syncthreads();
        }
    }

    // ---- exact split-KV merge across wn pairs (reuse K buffer smem) ----
    __syncthreads();
    float* mrg = (float*)Ks;
    const int mbase = wm * 4352 + lane * 136;
    if (wn == 1) {
        #pragma unroll
        for (int i = 0; i < 2; i++)
            #pragma unroll
            for (int n = 0; n < 16; n++)
                #pragma unroll
                for (int c = 0; c < 4; c++)
                    mrg[mbase + (i * 16 + n) * 4 + c] = oac[i][n][c];
        #pragma unroll
        for (int s = 0; s < 4; s++) {
            mrg[mbase + 128 + s] = mst[s];
            mrg[mbase + 132 + s] = lst[s];
        }
    }
    __syncthreads();
    if (wn == 0) {
        float scS[4], scO[4], lm[4];
        #pragma unroll
        for (int s = 0; s < 4; s++) {
            float pm = mrg[mbase + 128 + s];
            float pv = mrg[mbase + 132 + s];
            float mm = fmaxf(mst[s], pm);
            scS[s] = __expf(mst[s] - mm);
            scO[s] = __expf(pm - mm);
            lm[s] = lst[s] * scS[s] + pv * scO[s];
        }
        #pragma unroll
        for (int i = 0; i < 2; i++) {
            float rl0 = 1.f / lm[2 * i], rl1 = 1.f / lm[2 * i + 1];
            long long r0 = qrow0 + mrow + i * 16 + gid;
            uint2* op0 = catp2 + r0 * 768 + h * 64;
            uint2* op1 = op0 + 8LL * 768;
            #pragma unroll
            for (int n = 0; n < 16; n++) {
                const float* po = &mrg[mbase + (i * 16 + n) * 4];
                float o0 = oac[i][n][0] * scS[2 * i]     + po[0] * scO[2 * i];
                float o1 = oac[i][n][1] * scS[2 * i]     + po[1] * scO[2 * i];
                float o2 = oac[i][n][2] * scS[2 * i + 1] + po[2] * scO[2 * i + 1];
                float o3 = oac[i][n][3] * scS[2 * i + 1] + po[3] * scO[2 * i + 1];
                op0[4 * n + tig] = packpair(o0 * rl0, o1 * rl0);
                op1[4 * n + tig] = packpair(o2 * rl1, o3 * rl1);
            }
        }
    }
}

// ============================================================================
// row softmax + pack to F1 (cultural branch)
// ============================================================================
__global__ void __launch_bounds__(256) softmax_pack(const float* __restrict__ in,
                                                    uint2* __restrict__ out)
{
    const long long row = blockIdx.x;
    const float2* r = (const float2*)(in + row * S_LEN);
    uint2* o = out + row * (S_LEN / 2);
    const int tid = threadIdx.x;
    __shared__ float red[256];

    float2 v[4];
    float mx = -1e30f;
    #pragma unroll
    for (int i = 0; i < 4; i++) {
        v[i] = r[tid + i * 256];
        mx = fmaxf(mx, fmaxf(v[i].x, v[i].y));
    }
    red[tid] = mx; __syncthreads();
    for (int s = 128; s > 0; s >>= 1) {
        if (tid < s) red[tid] = fmaxf(red[tid], red[tid + s]);
        __syncthreads();
    }
    mx = red[0];
    __syncthreads();

    float sum = 0.f;
    #pragma unroll
    for (int i = 0; i < 4; i++) {
        v[i].x = __expf(v[i].x - mx);
        v[i].y = __expf(v[i].y - mx);
        sum += v[i].x + v[i].y;
    }
    red[tid] = sum; __syncthreads();
    for (int s = 128; s > 0; s >>= 1) {
        if (tid < s) red[tid] += red[tid + s];
        __syncthreads();
    }
    const float inv = 1.0f / red[0];
    #pragma unroll
    for (int i = 0; i < 4; i++)
        o[tid + i * 256] = packpair(v[i].x * inv, v[i].y * inv);
}

// ============================================================================
template <typename T>
static T* symaddr(const void* s) {
    void* p = nullptr;
    cudaGetSymbolAddress(&p, s);
    return (T*)p;
}

extern "C" void kernel_launch(void* const* d_in, const int* in_sizes, int n_in,
                              void* d_out, int out_size)
{
    const float* x    = (const float*)d_in[0];
    const float* cm   = (const float*)d_in[1];
    const float* am   = (const float*)d_in[2];
    const float* rq_w = (const float*)d_in[3];
    const float* rk_w = (const float*)d_in[4];
    const float* rv_w = (const float*)d_in[5];
    const float* ro_w = (const float*)d_in[6];
    const float* cq_w = (const float*)d_in[7];
    const float* ck_w = (const float*)d_in[8];
    const float* cv_w = (const float*)d_in[9];
    const float* co_w = (const float*)d_in[10];
    const float* rq_b = (const float*)d_in[11];
    const float* rk_b = (const float*)d_in[12];
    const float* rv_b = (const float*)d_in[13];
    const float* ro_b = (const float*)d_in[14];
    const float* cq_b = (const float*)d_in[15];
    const float* ck_b = (const float*)d_in[16];
    const float* cv_b = (const float*)d_in[17];
    const float* co_b = (const float*)d_in[18];
    const float* r_cb = (const float*)d_in[19];
    const float* c_cb = (const float*)d_in[20];
    const float* out_w = (const float*)d_in[21];
    const float* out_b = (const float*)d_in[22];
    float* out = (float*)d_out;

    uint2* xp    = symaddr<uint2>(g_xp);
    uint2* wqkvp = symaddr<uint2>(g_wqkvp);
    float* bqkv  = symaddr<float>(g_bqkv);
    uint2* qkvp  = symaddr<uint2>(g_qkvp);
    uint2* vf2   = symaddr<uint2>(g_vf2);
    float* sc    = symaddr<float>(g_sc);
    uint2* scp   = symaddr<uint2>(g_scp);
    uint2* catp2 = symaddr<uint2>(g_catp2);
    uint2* rowp  = symaddr<uint2>(g_rowp);
    uint2* cowp  = symaddr<uint2>(g_cowp);
    uint2* outwp = symaddr<uint2>(g_outwp);
    float* w1f   = symaddr<float>(g_w1f);
    float* w2f   = symaddr<float>(g_w2f);
    uint2* fwp   = symaddr<uint2>(g_fwp);
    float* biasf = symaddr<float>(g_biasf);

    // ---- one-time host-object setup (streams/events cached across calls so
    // no driver allocations occur after the harness's pre-capture baseline) ----
    static bool s_init = false;
    static cudaStream_t s2, s3;
    static cudaEvent_t evStart, evFork, evV, evJoin2, evJoin3;
    if (!s_init) {
        cudaStreamCreateWithFlags(&s2, cudaStreamNonBlocking);
        cudaStreamCreateWithFlags(&s3, cudaStreamNonBlocking);
        cudaEventCreateWithFlags(&evStart, cudaEventDisableTiming);
        cudaEventCreateWithFlags(&evFork, cudaEventDisableTiming);
        cudaEventCreateWithFlags(&evV, cudaEventDisableTiming);
        cudaEventCreateWithFlags(&evJoin2, cudaEventDisableTiming);
        cudaEventCreateWithFlags(&evJoin3, cudaEventDisableTiming);
        cudaFuncSetAttribute(flash_reg, cudaFuncAttributeMaxDynamicSharedMemorySize, FLASH_SMEM);
        s_init = true;
    }

    dim3 blk(128);

    // ---- fork s3 FROM the capturing stream ----
    cudaEventRecord(evStart, 0);
    cudaStreamWaitEvent(s3, evStart, 0);

    // ---- s3: output-weight fusion (depends only on weight inputs) ----
    {
        const int tot66 = 384 * 768;
        split_f1<<<(294912 + 255) / 256, 256, 0, s3>>>(ro_w, rowp, 294912);
        split_f1<<<(294912 + 255) / 256, 256, 0, s3>>>(co_w, cowp, 294912);
        pack_f2<<<(768 * 768 + 255) / 256, 256, 0, s3>>>(out_w, outwp, 768, 768, 0, 768 * 768);
        dim3 gw(768 / 64, 768 / 128, 1);
        gemm_bf3_nn<<<gw, blk, 0, s3>>>(rowp, outwp, w1f, nullptr, nullptr,
                                        768, 384, 768, 768, 0,
                                        0, 0, 0, 0, 0, 1);
        gemm_bf3_nn<<<gw, blk, 0, s3>>>(cowp, outwp + (size_t)384 * 768, w2f, nullptr, nullptr,
                                        768, 384, 768, 768, 0,
                                        0, 0, 0, 0, 0, 1);
        pack_f2<<<(tot66 + 255) / 256, 256, 0, s3>>>(w1f, fwp, 768, 768, 0, tot66);
        pack_f2<<<(tot66 + 255) / 256, 256, 0, s3>>>(w2f, fwp + (size_t)384 * 768, 768, 768, 0, tot66);
        fuse_bias<<<3, 256, 0, s3>>>(ro_b, co_b, out_w, out_b, biasf);
        cudaEventRecord(evJoin3, s3);
    }

    // ---- main: QKV weight/bias/x packs ----
    {
        dim3 g6((384 * 768 + 255) / 256, 6);
        pack_w6<<<g6, 256>>>(rq_w, rk_w, rv_w, cq_w, ck_w, cv_w, wqkvp);
        fold_bias<<<(NQKV + 255) / 256, 256>>>(rq_b, rk_b, rv_b, cq_b, ck_b, cv_b,
                                               r_cb, c_cb, bqkv);
        const int tp = M_TOT * 384;
        split_f1<<<(tp + 255) / 256, 256>>>(x, xp, tp);
    }

    // ---- fused QKV projection ----
    dim3 gq(NQKV / 64, M_TOT / 128, 1);
    gemm_bf3_nn<<<gq, blk>>>(xp, wqkvp, nullptr, qkvp, bqkv,
                             E_DIM, 384, NQKV, 0, 2304,
                             0, 0, 0, 0, 0, 1);

    // ---- fork: cultural scores+softmax need only qkvp ----
    cudaEventRecord(evFork, 0);
    cudaStreamWaitEvent(s2, evFork, 0);
    {
        const float scale_c = 1.0f / sqrtf((float)HD_C);
        dim3 gsc(S_LEN / 64, S_LEN / 128, B_SZ * NH_C);
        gemm_bf3_nt_scores<<<gsc, blk, 0, s2>>>(qkvp + 1152, qkvp + 1536, sc,
                                                am, cm, scale_c, HD_C, NH_C, 2304);
        softmax_pack<<<B_SZ * NH_C * S_LEN, 256, 0, s2>>>(sc, scp);
    }

    // ---- main: split V, then flash (writes att_reg into catp2 cols 0-383) ----
    {
        const int tv = B_SZ * 1024 * 1536;
        split_v<<<(tv + 255) / 256, 256>>>(qkvp, vf2);
        cudaEventRecord(evV, 0);

        const float scale_r = 1.0f / sqrtf((float)HD_R);
        dim3 gf(16, B_SZ * NH_R);
        flash_reg<<<gf, 256, FLASH_SMEM>>>(qkvp, vf2, am, catp2, scale_r);
    }

    // ---- side: cultural PV writes att_cul into catp2 cols 384-767 ----
    {
        cudaStreamWaitEvent(s2, evV, 0);
        dim3 gac(HD_C / 64, S_LEN / 128, B_SZ * NH_C);
        gemm_bf3_nn<<<gac, blk, 0, s2>>>(scp, vf2 + 768, nullptr, catp2 + 384, nullptr,
                                         S_LEN, 1024, 1536, 0, 768,
                                         (long long)S_LEN * 1024,
                                         (long long)1024 * 1536, HD_C,
                                         (long long)S_LEN * 768, HD_C / 2, NH_C);
        cudaEventRecord(evJoin2, s2);
    }

    // ---- join both side streams ----
    cudaStreamWaitEvent(0, evJoin2, 0);
    cudaStreamWaitEvent(0, evJoin3, 0);

    // ---- fused final: out = [att_reg|att_cul] @ [W1;W2] + biasf ----
    dim3 gp(E_DIM / 64, M_TOT / 128, 1);
    gemm_bf3_nn<<<gp, blk>>>(catp2, fwp, out, nullptr, biasf,
                             2 * E_DIM, 768, 768, 768, 0,
                             0, 0, 0, 0, 0, 1);
}

// round 13
// speedup vs baseline: 1.5759x; 1.0953x over previous
#include <cuda_runtime.h>
#include <cuda_bf16.h>
#include <math.h>
#include <stdint.h>

#define S_LEN 2048
#define E_DIM 768
#define B_SZ  2
#define NH_R  6
#define NH_C  2
#define HD_R  128
#define HD_C  384
#define M_TOT 4096
#define NQKV  4608

// smem strides (uint2 units)
#define SP_A  20
#define SP_BT 20
#define SB_B  132        // gemm128 B stage: 16 p-rows x 128 cols
#define GA_ST (128*SP_A)
#define GB_ST (16*SB_B)
#define G_STAGE (GA_ST + GB_ST)
#define GEMM_SMEM (2*G_STAGE*8)   // 74,752 B

// flash smem geometry (uint2 units)
#define FQ_S 68
#define FK_S 68
#define FV_S 132
#define FQ_SZ (128*FQ_S)
#define FK_SZ (64*FK_S)
#define FV_SZ (32*FV_S)
#define FLASH_SMEM ((FQ_SZ + 2*FK_SZ + 2*FV_SZ)*8 + 2*64*4)   // 207,360 B

// -------- scratch ------------------------------------------------------------
__device__ uint2 g_xp[(size_t)M_TOT*384];
__device__ uint2 g_wqkvp[(size_t)384*NQKV];
__device__ float g_bqkv[NQKV];
__device__ uint2 g_qkvp[(size_t)M_TOT*2304];
__device__ uint2 g_vf2[(size_t)B_SZ*1024*1536];
__device__ float g_sc[(size_t)B_SZ*NH_C*S_LEN*S_LEN];
__device__ uint2 g_scp[(size_t)B_SZ*NH_C*S_LEN*1024];
__device__ uint2 g_catp2[(size_t)M_TOT*768];        // A' = [att_reg | att_cul] F1
// weight-fusion scratch
__device__ uint2 g_rowp[(size_t)768*384];
__device__ uint2 g_cowp[(size_t)768*384];
__device__ uint2 g_outwp[(size_t)768*768];
__device__ float g_w1f[(size_t)768*768];
__device__ float g_w2f[(size_t)768*768];
__device__ uint2 g_fwp[(size_t)768*768];
__device__ float g_biasf[768];

// -------- helpers --------------------------------------------------------------
__device__ __forceinline__ uint32_t smem_u32(const void* p) {
    return (uint32_t)__cvta_generic_to_shared(p);
}
#define CP16(sa, ga) asm volatile("cp.async.cg.shared.global [%0], [%1], 16;" :: "r"(sa), "l"(ga))
#define CP_COMMIT()  asm volatile("cp.async.commit_group;" ::: "memory")
#define CP_WAIT0()   asm volatile("cp.async.wait_group 0;" ::: "memory")

__device__ __forceinline__ uint32_t bf2w(float a, float b) {
    __nv_bfloat162 t;
    t.x = __float2bfloat16(a); t.y = __float2bfloat16(b);
    return *reinterpret_cast<uint32_t*>(&t);
}
__device__ __forceinline__ uint2 packpair(float e, float o) {
    __nv_bfloat16 he = __float2bfloat16(e);
    __nv_bfloat16 ho = __float2bfloat16(o);
    float le = e - __bfloat162float(he);
    float lo = o - __bfloat162float(ho);
    uint2 r;
    __nv_bfloat162 th; th.x = he; th.y = ho;
    r.x = *reinterpret_cast<uint32_t*>(&th);
    r.y = bf2w(le, lo);
    return r;
}

__device__ __forceinline__ void mma_bf16(float* c, const uint32_t* a, const uint32_t* b) {
    asm volatile(
        "mma.sync.aligned.m16n8k16.row.col.f32.bf16.bf16.f32 "
        "{%0,%1,%2,%3}, {%4,%5,%6,%7}, {%8,%9}, {%0,%1,%2,%3};"
        : "+f"(c[0]), "+f"(c[1]), "+f"(c[2]), "+f"(c[3])
        : "r"(a[0]), "r"(a[1]), "r"(a[2]), "r"(a[3]), "r"(b[0]), "r"(b[1]));
}

// ============================================================================
// small packing kernels
// ============================================================================
__global__ void pack_w6(const float* __restrict__ w0, const float* __restrict__ w1,
                        const float* __restrict__ w2, const float* __restrict__ w3,
                        const float* __restrict__ w4, const float* __restrict__ w5,
                        uint2* __restrict__ wqkvp)
{
    const int blk = blockIdx.y;
    const float* w;
    switch (blk) {
        case 0: w = w0; break; case 1: w = w1; break; case 2: w = w2; break;
        case 3: w = w3; break; case 4: w = w4; break; default: w = w5; break;
    }
    int idx = blockIdx.x * 256 + threadIdx.x;
    if (idx >= 384 * 768) return;
    int p = idx / 768, n = idx % 768;
    wqkvp[(long long)p * NQKV + blk * 768 + n] =
        packpair(w[(long long)(2 * p) * 768 + n], w[(long long)(2 * p + 1) * 768 + n]);
}

__global__ void pack_f2(const float* __restrict__ src, uint2* __restrict__ dst,
                        int Nsrc, int dstN, int col_off, int total)
{
    int idx = blockIdx.x * 256 + threadIdx.x;
    if (idx >= total) return;
    int p = idx / Nsrc, n = idx % Nsrc;
    dst[(long long)p * dstN + col_off + n] =
        packpair(src[(long long)(2 * p) * Nsrc + n], src[(long long)(2 * p + 1) * Nsrc + n]);
}

__global__ void fold_bias(const float* b0, const float* b1, const float* b2,
                          const float* b3, const float* b4, const float* b5,
                          const float* rcb, const float* ccb, float* Bv)
{
    int idx = blockIdx.x * 256 + threadIdx.x;
    if (idx >= NQKV) return;
    int blk = idx / E_DIM, c = idx % E_DIM;
    const float* bs;
    switch (blk) {
        case 0: bs = b0; break; case 1: bs = b1; break; case 2: bs = b2; break;
        case 3: bs = b3; break; case 4: bs = b4; break; default: bs = b5; break;
    }
    float v = bs[c];
    if (blk == 0) v += rcb[c];
    if (blk == 3) v += ccb[c];
    Bv[idx] = v;
}

__global__ void split_f1(const float* __restrict__ src, uint2* __restrict__ dst, int totalPairs)
{
    int idx = blockIdx.x * 256 + threadIdx.x;
    if (idx >= totalPairs) return;
    float2 f = ((const float2*)src)[idx];
    dst[idx] = packpair(f.x, f.y);
}

__global__ void fuse_bias(const float* __restrict__ ro_b, const float* __restrict__ co_b,
                          const float* __restrict__ out_w, const float* __restrict__ out_b,
                          float* __restrict__ biasf)
{
    int n = blockIdx.x * 256 + threadIdx.x;
    if (n >= 768) return;
    float s = out_b[n];
    for (int j = 0; j < 768; j++) {
        s += ro_b[j] * out_w[(long long)j * 768 + n];
        s += co_b[j] * out_w[(long long)(768 + j) * 768 + n];
    }
    biasf[n] = s;
}

__global__ void split_v(const uint2* __restrict__ qkvp, uint2* __restrict__ v)
{
    int idx = blockIdx.x * 256 + threadIdx.x;
    const int total = B_SZ * 1024 * 1536;
    if (idx >= total) return;
    int b = idx / (1024 * 1536);
    int r = idx % (1024 * 1536);
    int p = r / 1536, n = r % 1536;
    int col = (n < 768) ? (1536 + n) : (3072 + n);
    int cp = col >> 1, half = col & 1;
    const uint2 w0 = qkvp[(size_t)(b * 2048 + 2 * p) * 2304 + cp];
    const uint2 w1 = qkvp[(size_t)(b * 2048 + 2 * p + 1) * 2304 + cp];
    __nv_bfloat162 h0 = *(const __nv_bfloat162*)&w0.x;
    __nv_bfloat162 l0 = *(const __nv_bfloat162*)&w0.y;
    __nv_bfloat162 h1 = *(const __nv_bfloat162*)&w1.x;
    __nv_bfloat162 l1 = *(const __nv_bfloat162*)&w1.y;
    float e = half ? (__bfloat162float(h0.y) + __bfloat162float(l0.y))
                   : (__bfloat162float(h0.x) + __bfloat162float(l0.x));
    float o = half ? (__bfloat162float(h1.y) + __bfloat162float(l1.y))
                   : (__bfloat162float(h1.x) + __bfloat162float(l1.x));
    v[idx] = packpair(e, o);
}

// ============================================================================
// NN GEMM v2, bf16x3: tile 128x128x32, 4 warps (warp tile 64x64),
// cp.async double-buffered smem. LDS/MMA = 0.33 (vs 0.5 before).
// ============================================================================
__global__ void __launch_bounds__(128, 2) gemm_bf3_128(
    const uint2* __restrict__ A, const uint2* __restrict__ B,
    float* __restrict__ Cf, uint2* __restrict__ Cp,
    const float* __restrict__ bias,
    int K, int lda2, int ldbN, int ldc, int ldc2,
    long long sA2, long long sBb, long long sBh,
    long long sCpb, long long sCph, int nh)
{
    extern __shared__ uint2 gsm[];
    const int tid = threadIdx.x;
    const int wid = tid >> 5, lane = tid & 31;
    const int gid = lane >> 2, tig = lane & 3;
    const int wm = wid >> 1, wn = wid & 1;
    const int z = blockIdx.z, b = z / nh, h = z % nh;
    const uint2* Ap = A + (long long)z * sA2;
    const uint2* Bp = B + (long long)b * sBb + (long long)h * sBh;
    const int row0 = blockIdx.y * 128, col0 = blockIdx.x * 128;

    // stage loader: A (128 rows x 16 pairs) + B (16 p-rows x 128 cols)
    auto load_stage = [&](int s, int k0) {
        uint2* As = gsm + s * G_STAGE;
        uint2* Bs = As + GA_ST;
        const int kp = k0 >> 1;
        #pragma unroll
        for (int it = 0; it < 8; it++) {
            int lin = it * 128 + tid;
            int m = lin >> 3, p2 = (lin & 7) << 1;
            CP16(smem_u32(&As[m * SP_A + p2]),
                 Ap + (long long)(row0 + m) * lda2 + kp + p2);
        }
        #pragma unroll
        for (int it = 0; it < 8; it++) {
            int lin = it * 128 + tid;
            int p = lin >> 6, c2 = (lin & 63) << 1;
            CP16(smem_u32(&Bs[p * SB_B + c2]),
                 Bp + (long long)(kp + p) * ldbN + col0 + c2);
        }
        CP_COMMIT();
    };

    float acc[4][8][4] = {};

    load_stage(0, 0);
    CP_WAIT0();
    __syncthreads();

    const int niter = K / 32;
    for (int i0 = 0; i0 < niter; i0++) {
        int buf = i0 & 1;
        if (i0 + 1 < niter) load_stage(buf ^ 1, (i0 + 1) * 32);

        const uint2* As = gsm + buf * G_STAGE;
        const uint2* Bs = As + GA_ST;
        #pragma unroll
        for (int pb2 = 0; pb2 < 16; pb2 += 8) {
            uint32_t bh[8][2], bl[8][2];
            #pragma unroll
            for (int j = 0; j < 8; j++) {
                int n = wn * 64 + j * 8 + gid;
                uint2 e0 = Bs[(pb2 + tig) * SB_B + n];
                uint2 e1 = Bs[(pb2 + tig + 4) * SB_B + n];
                bh[j][0] = e0.x; bl[j][0] = e0.y;
                bh[j][1] = e1.x; bl[j][1] = e1.y;
            }
            #pragma unroll
            for (int i = 0; i < 4; i++) {
                int mb = wm * 64 + i * 16 + gid;
                uint2 a0 = As[mb * SP_A + pb2 + tig];
                uint2 a1 = As[(mb + 8) * SP_A + pb2 + tig];
                uint2 a2 = As[mb * SP_A + pb2 + tig + 4];
                uint2 a3 = As[(mb + 8) * SP_A + pb2 + tig + 4];
                uint32_t ah[4] = {a0.x, a1.x, a2.x, a3.x};
                uint32_t al[4] = {a0.y, a1.y, a2.y, a3.y};
                #pragma unroll
                for (int j = 0; j < 8; j++) {
                    mma_bf16(acc[i][j], ah, bh[j]);
                    mma_bf16(acc[i][j], al, bh[j]);
                    mma_bf16(acc[i][j], ah, bl[j]);
                }
            }
        }
        if (i0 + 1 < niter) {
            CP_WAIT0();
            __syncthreads();
        }
    }

    uint2* Cpb = Cp ? (Cp + (long long)b * sCpb + (long long)h * sCph) : nullptr;
    #pragma unroll
    for (int i = 0; i < 4; i++) {
        int r0 = row0 + wm * 64 + i * 16 + gid;
        #pragma unroll
        for (int j = 0; j < 8; j++) {
            int c = col0 + wn * 64 + j * 8 + tig * 2;
            float b0 = 0.f, b1 = 0.f;
            if (bias) { b0 = bias[c]; b1 = bias[c + 1]; }
            float v00 = acc[i][j][0] + b0, v01 = acc[i][j][1] + b1;
            float v10 = acc[i][j][2] + b0, v11 = acc[i][j][3] + b1;
            if (Cf) {
                float2 t0 = {v00, v01}, t1 = {v10, v11};
                *(float2*)(Cf + (long long)r0 * ldc + c) = t0;
                *(float2*)(Cf + (long long)(r0 + 8) * ldc + c) = t1;
            }
            if (Cpb) {
                Cpb[(long long)r0 * ldc2 + (c >> 1)] = packpair(v00, v01);
                Cpb[(long long)(r0 + 8) * ldc2 + (c >> 1)] = packpair(v10, v11);
            }
        }
    }
}

// ============================================================================
// NT scores GEMM (cultural branch only; round-12 validated)
// ============================================================================
__global__ void __launch_bounds__(128) gemm_bf3_nt_scores(
    const uint2* __restrict__ Qb, const uint2* __restrict__ Kb,
    float* __restrict__ Sc,
    const float* __restrict__ am, const float* __restrict__ cm,
    float scale, int hd, int nh, int lda2)
{
    __shared__ uint2 As[128 * SP_A];
    __shared__ uint2 Bs[64 * SP_BT];
    const int tid = threadIdx.x;
    const int wid = tid >> 5, lane = tid & 31;
    const int gid = lane >> 2, tig = lane & 3;
    const int wm = wid >> 1, wn = wid & 1;
    const int z = blockIdx.z, b = z / nh, h = z % nh;
    const int hp = hd >> 1;
    const uint2* Qp = Qb + (long long)b * S_LEN * lda2 + h * hp;
    const uint2* Kp = Kb + (long long)b * S_LEN * lda2 + h * hp;
    float* Cpt = Sc + (long long)z * S_LEN * S_LEN;
    const int row0 = blockIdx.y * 128, col0 = blockIdx.x * 64;

    uint4 pa[8], pbuf[4];
    #pragma unroll
    for (int it = 0; it < 8; it++) {
        int lin = it * 128 + tid; int m = lin >> 3, p4 = (lin & 7) << 1;
        pa[it] = *(const uint4*)(Qp + (long long)(row0 + m) * lda2 + p4);
    }
    #pragma unroll
    for (int it = 0; it < 4; it++) {
        int lin = it * 128 + tid; int n = lin >> 3, p4 = (lin & 7) << 1;
        pbuf[it] = *(const uint4*)(Kp + (long long)(col0 + n) * lda2 + p4);
    }

    float acc[4][4][4] = {};

    for (int k0 = 0; k0 < hd; k0 += 32) {
        #pragma unroll
        for (int it = 0; it < 8; it++) {
            int lin = it * 128 + tid; int m = lin >> 3, p4 = (lin & 7) << 1;
            *(uint4*)&As[m * SP_A + p4] = pa[it];
        }
        #pragma unroll
        for (int it = 0; it < 4; it++) {
            int lin = it * 128 + tid; int n = lin >> 3, p4 = (lin & 7) << 1;
            *(uint4*)&Bs[n * SP_BT + p4] = pbuf[it];
        }
        __syncthreads();
        if (k0 + 32 < hd) {
            int k02 = (k0 + 32) >> 1;
            #pragma unroll
            for (int it = 0; it < 8; it++) {
                int lin = it * 128 + tid; int m = lin >> 3, p4 = (lin & 7) << 1;
                pa[it] = *(const uint4*)(Qp + (long long)(row0 + m) * lda2 + k02 + p4);
            }
            #pragma unroll
            for (int it = 0; it < 4; it++) {
                int lin = it * 128 + tid; int n = lin >> 3, p4 = (lin & 7) << 1;
                pbuf[it] = *(const uint4*)(Kp + (long long)(col0 + n) * lda2 + k02 + p4);
            }
        }
        #pragma unroll
        for (int pb2 = 0; pb2 < 16; pb2 += 8) {
            uint32_t bh[4][2], bl[4][2];
            #pragma unroll
            for (int j = 0; j < 4; j++) {
                int n = wn * 32 + j * 8 + gid;
                uint2 e0 = Bs[n * SP_BT + pb2 + tig];
                uint2 e1 = Bs[n * SP_BT + pb2 + tig + 4];
                bh[j][0] = e0.x; bl[j][0] = e0.y;
                bh[j][1] = e1.x; bl[j][1] = e1.y;
            }
            #pragma unroll
            for (int i = 0; i < 4; i++) {
                int mb = wm * 64 + i * 16 + gid;
                uint2 a0 = As[mb * SP_A + pb2 + tig];
                uint2 a1 = As[(mb + 8) * SP_A + pb2 + tig];
                uint2 a2 = As[mb * SP_A + pb2 + tig + 4];
                uint2 a3 = As[(mb + 8) * SP_A + pb2 + tig + 4];
                uint32_t ah[4] = {a0.x, a1.x, a2.x, a3.x};
                uint32_t al[4] = {a0.y, a1.y, a2.y, a3.y};
                #pragma unroll
                for (int j = 0; j < 4; j++) {
                    mma_bf16(acc[i][j], ah, bh[j]);
                    mma_bf16(acc[i][j], al, bh[j]);
                    mma_bf16(acc[i][j], ah, bl[j]);
                }
            }
        }
        __syncthreads();
    }

    #pragma unroll
    for (int i = 0; i < 4; i++) {
        int t0 = row0 + wm * 64 + i * 16 + gid;
        #pragma unroll
        for (int j = 0; j < 4; j++) {
            int s = col0 + wn * 32 + j * 8 + tig * 2;
            float m0 = am[b * S_LEN + s], m1 = am[b * S_LEN + s + 1];
            float n0 = m0, n1 = m1;
            if (cm) {
                const float* cmr0 = cm + ((long long)b * S_LEN + t0) * S_LEN;
                const float* cmr1 = cmr0 + 8LL * S_LEN;
                m0 += cmr0[s]; m1 += cmr0[s + 1];
                n0 += cmr1[s]; n1 += cmr1[s + 1];
            }
            float2 v0 = { acc[i][j][0] * scale + m0, acc[i][j][1] * scale + m1 };
            float2 v1 = { acc[i][j][2] * scale + n0, acc[i][j][3] * scale + n1 };
            *(float2*)(Cpt + (long long)t0 * S_LEN + s) = v0;
            *(float2*)(Cpt + (long long)(t0 + 8) * S_LEN + s) = v1;
        }
    }
}

// ============================================================================
// Flash-fused regular branch (round-12 validated)
// ============================================================================
__global__ void __launch_bounds__(256, 1) flash_reg(
    const uint2* __restrict__ qkvp, const uint2* __restrict__ vf2,
    const float* __restrict__ am, uint2* __restrict__ catp2, float scale)
{
    extern __shared__ uint2 sm[];
    uint2* Qs = sm;
    uint2* Ks = Qs + FQ_SZ;
    uint2* Vs = Ks + 2 * FK_SZ;
    float* ams = (float*)(Vs + 2 * FV_SZ);

    const int tid = threadIdx.x, wid = tid >> 5, lane = tid & 31;
    const int gid = lane >> 2, tig = lane & 3;
    const int wm = wid >> 1, wn = wid & 1;
    const int qt = blockIdx.x;
    const int z = blockIdx.y, b = z / NH_R, h = z % NH_R;

    const long long qrow0 = (long long)b * S_LEN + qt * 128;
    const uint2* Qg = qkvp + qrow0 * 2304 + h * 64;
    const uint2* Kg = qkvp + (long long)b * S_LEN * 2304 + 384 + h * 64;
    const uint2* Vg = vf2 + (long long)b * 1024 * 1536 + h * 128;
    const float* amb = am + (long long)b * S_LEN;

    #pragma unroll
    for (int it = 0; it < 16; it++) {
        int lin = it * 256 + tid;
        int r = lin >> 5, p2 = (lin & 31) << 1;
        CP16(smem_u32(&Qs[r * FQ_S + p2]), Qg + (long long)r * 2304 + p2);
    }
    #pragma unroll
    for (int it = 0; it < 8; it++) {
        int lin = it * 256 + tid;
        int r = lin >> 5, p2 = (lin & 31) << 1;
        CP16(smem_u32(&Ks[r * FK_S + p2]), Kg + (long long)r * 2304 + p2);
    }
    #pragma unroll
    for (int it = 0; it < 8; it++) {
        int lin = it * 256 + tid;
        int p = lin >> 6, n2 = (lin & 63) << 1;
        CP16(smem_u32(&Vs[p * FV_S + n2]), Vg + (long long)p * 1536 + n2);
    }
    if (tid < 16) CP16(smem_u32(&ams[tid * 4]), amb + tid * 4);
    CP_COMMIT();

    float oac[2][16][4] = {};
    float mst[4] = {-1e30f, -1e30f, -1e30f, -1e30f};
    float lst[4] = {0.f, 0.f, 0.f, 0.f};
    const int mrow = wm * 32;

    CP_WAIT0();
    __syncthreads();

    for (int kt = 0; kt < 32; kt++) {
        if (kt + 1 < 32) {
            int nb = (kt + 1) & 1;
            uint2* Kd = Ks + nb * FK_SZ;
            uint2* Vd = Vs + nb * FV_SZ;
            #pragma unroll
            for (int it = 0; it < 8; it++) {
                int lin = it * 256 + tid;
                int r = lin >> 5, p2 = (lin & 31) << 1;
                CP16(smem_u32(&Kd[r * FK_S + p2]),
                     Kg + (long long)((kt + 1) * 64 + r) * 2304 + p2);
            }
            #pragma unroll
            for (int it = 0; it < 8; it++) {
                int lin = it * 256 + tid;
                int p = lin >> 6, n2 = (lin & 63) << 1;
                CP16(smem_u32(&Vd[p * FV_S + n2]),
                     Vg + (long long)((kt + 1) * 32 + p) * 1536 + n2);
            }
            if (tid < 16)
                CP16(smem_u32(&ams[nb * 64 + tid * 4]), amb + (kt + 1) * 64 + tid * 4);
            CP_COMMIT();
        }

        const uint2* Kb = Ks + (kt & 1) * FK_SZ;
        const uint2* Vb = Vs + (kt & 1) * FV_SZ;
        const float* amc = ams + (kt & 1) * 64;

        float sac[2][4][4] = {};
        #pragma unroll
        for (int t = 0; t < 8; t++) {
            uint32_t ah[2][4], al[2][4];
            #pragma unroll
            for (int i = 0; i < 2; i++) {
                int mr = mrow + i * 16 + gid;
                uint2 a0 = Qs[mr * FQ_S + 8 * t + tig];
                uint2 a1 = Qs[(mr + 8) * FQ_S + 8 * t + tig];
                uint2 a2 = Qs[mr * FQ_S + 8 * t + tig + 4];
                uint2 a3 = Qs[(mr + 8) * FQ_S + 8 * t + tig + 4];
                ah[i][0] = a0.x; ah[i][1] = a1.x; ah[i][2] = a2.x; ah[i][3] = a3.x;
                al[i][0] = a0.y; al[i][1] = a1.y; al[i][2] = a2.y; al[i][3] = a3.y;
            }
            #pragma unroll
            for (int j = 0; j < 4; j++) {
                int n = wn * 32 + j * 8 + gid;
                uint2 e0 = Kb[n * FK_S + 8 * t + tig];
                uint2 e1 = Kb[n * FK_S + 8 * t + tig + 4];
                uint32_t bh[2] = {e0.x, e1.x};
                uint32_t bl[2] = {e0.y, e1.y};
                #pragma unroll
                for (int i = 0; i < 2; i++) {
                    mma_bf16(sac[i][j], ah[i], bh);
                    mma_bf16(sac[i][j], al[i], bh);
                    mma_bf16(sac[i][j], ah[i], bl);
                }
            }
        }

        uint32_t ph[2][2][4], pl[2][2][4];
        #pragma unroll
        for (int i = 0; i < 2; i++) {
            float mx0 = -1e30f, mx1 = -1e30f;
            #pragma unroll
            for (int j = 0; j < 4; j++) {
                float a0 = amc[wn * 32 + 8 * j + 2 * tig];
                float a1 = amc[wn * 32 + 8 * j + 2 * tig + 1];
                sac[i][j][0] = sac[i][j][0] * scale + a0;
                sac[i][j][1] = sac[i][j][1] * scale + a1;
                sac[i][j][2] = sac[i][j][2] * scale + a0;
                sac[i][j][3] = sac[i][j][3] * scale + a1;
                mx0 = fmaxf(mx0, fmaxf(sac[i][j][0], sac[i][j][1]));
                mx1 = fmaxf(mx1, fmaxf(sac[i][j][2], sac[i][j][3]));
            }
            mx0 = fmaxf(mx0, __shfl_xor_sync(0xffffffffu, mx0, 1));
            mx0 = fmaxf(mx0, __shfl_xor_sync(0xffffffffu, mx0, 2));
            mx1 = fmaxf(mx1, __shfl_xor_sync(0xffffffffu, mx1, 1));
            mx1 = fmaxf(mx1, __shfl_xor_sync(0xffffffffu, mx1, 2));
            float mn0 = fmaxf(mst[2 * i], mx0), mn1 = fmaxf(mst[2 * i + 1], mx1);
            float sc0 = __expf(mst[2 * i] - mn0), sc1 = __expf(mst[2 * i + 1] - mn1);
            float ps0 = 0.f, ps1 = 0.f;
            #pragma unroll
            for (int j = 0; j < 4; j++) {
                sac[i][j][0] = __expf(sac[i][j][0] - mn0);
                sac[i][j][1] = __expf(sac[i][j][1] - mn0);
                sac[i][j][2] = __expf(sac[i][j][2] - mn1);
                sac[i][j][3] = __expf(sac[i][j][3] - mn1);
                ps0 += sac[i][j][0] + sac[i][j][1];
                ps1 += sac[i][j][2] + sac[i][j][3];
            }
            ps0 += __shfl_xor_sync(0xffffffffu, ps0, 1);
            ps0 += __shfl_xor_sync(0xffffffffu, ps0, 2);
            ps1 += __shfl_xor_sync(0xffffffffu, ps1, 1);
            ps1 += __shfl_xor_sync(0xffffffffu, ps1, 2);
            lst[2 * i]     = lst[2 * i] * sc0 + ps0;
            lst[2 * i + 1] = lst[2 * i + 1] * sc1 + ps1;
            mst[2 * i] = mn0; mst[2 * i + 1] = mn1;

            #pragma unroll
            for (int n = 0; n < 16; n++) {
                oac[i][n][0] *= sc0; oac[i][n][1] *= sc0;
                oac[i][n][2] *= sc1; oac[i][n][3] *= sc1;
            }

            #pragma unroll
            for (int t = 0; t < 2; t++) {
                uint2 w0 = packpair(sac[i][2 * t][0], sac[i][2 * t][1]);
                uint2 w1 = packpair(sac[i][2 * t][2], sac[i][2 * t][3]);
                uint2 w2 = packpair(sac[i][2 * t + 1][0], sac[i][2 * t + 1][1]);
                uint2 w3 = packpair(sac[i][2 * t + 1][2], sac[i][2 * t + 1][3]);
                ph[i][t][0] = w0.x; pl[i][t][0] = w0.y;
                ph[i][t][1] = w1.x; pl[i][t][1] = w1.y;
                ph[i][t][2] = w2.x; pl[i][t][2] = w2.y;
                ph[i][t][3] = w3.x; pl[i][t][3] = w3.y;
            }
        }

        #pragma unroll
        for (int t = 0; t < 2; t++) {
            int pt = 2 * wn + t;
            #pragma unroll
            for (int n = 0; n < 16; n++) {
                uint2 e0 = Vb[(8 * pt + tig) * FV_S + 8 * n + gid];
                uint2 e1 = Vb[(8 * pt + tig + 4) * FV_S + 8 * n + gid];
                uint32_t bh[2] = {e0.x, e1.x};
                uint32_t bl[2] = {e0.y, e1.y};
                #pragma unroll
                for (int i = 0; i < 2; i++) {
                    mma_bf16(oac[i][n], ph[i][t], bh);
                    mma_bf16(oac[i][n], pl[i][t], bh);
                    mma_bf16(oac[i][n], ph[i][t], bl);
                }
            }
        }

        if (kt + 1 < 32) {
            CP_WAIT0();
            __syncthreads();
        }
    }

    __syncthreads();
    float* mrg = (float*)Ks;
    const int mbase = wm * 4352 + lane * 136;
    if (wn == 1) {
        #pragma unroll
        for (int i = 0; i < 2; i++)
            #pragma unroll
            for (int n = 0; n < 16; n++)
                #pragma unroll
                for (int c = 0; c < 4; c++)
                    mrg[mbase + (i * 16 + n) * 4 + c] = oac[i][n][c];
        #pragma unroll
        for (int s = 0; s < 4; s++) {
            mrg[mbase + 128 + s] = mst[s];
            mrg[mbase + 132 + s] = lst[s];
        }
    }
    __syncthreads();
    if (wn == 0) {
        float scS[4], scO[4], lm[4];
        #pragma unroll
        for (int s = 0; s < 4; s++) {
            float pm = mrg[mbase + 128 + s];
            float pv = mrg[mbase + 132 + s];
            float mm = fmaxf(mst[s], pm);
            scS[s] = __expf(mst[s] - mm);
            scO[s] = __expf(pm - mm);
            lm[s] = lst[s] * scS[s] + pv * scO[s];
        }
        #pragma unroll
        for (int i = 0; i < 2; i++) {
            float rl0 = 1.f / lm[2 * i], rl1 = 1.f / lm[2 * i + 1];
            long long r0 = qrow0 + mrow + i * 16 + gid;
            uint2* op0 = catp2 + r0 * 768 + h * 64;
            uint2* op1 = op0 + 8LL * 768;
            #pragma unroll
            for (int n = 0; n < 16; n++) {
                const float* po = &mrg[mbase + (i * 16 + n) * 4];
                float o0 = oac[i][n][0] * scS[2 * i]     + po[0] * scO[2 * i];
                float o1 = oac[i][n][1] * scS[2 * i]     + po[1] * scO[2 * i];
                float o2 = oac[i][n][2] * scS[2 * i + 1] + po[2] * scO[2 * i + 1];
                float o3 = oac[i][n][3] * scS[2 * i + 1] + po[3] * scO[2 * i + 1];
                op0[4 * n + tig] = packpair(o0 * rl0, o1 * rl0);
                op1[4 * n + tig] = packpair(o2 * rl1, o3 * rl1);
            }
        }
    }
}

// ============================================================================
// row softmax + pack to F1 (cultural branch)
// ============================================================================
__global__ void __launch_bounds__(256) softmax_pack(const float* __restrict__ in,
                                                    uint2* __restrict__ out)
{
    const long long row = blockIdx.x;
    const float2* r = (const float2*)(in + row * S_LEN);
    uint2* o = out + row * (S_LEN / 2);
    const int tid = threadIdx.x;
    __shared__ float red[256];

    float2 v[4];
    float mx = -1e30f;
    #pragma unroll
    for (int i = 0; i < 4; i++) {
        v[i] = r[tid + i * 256];
        mx = fmaxf(mx, fmaxf(v[i].x, v[i].y));
    }
    red[tid] = mx; __syncthreads();
    for (int s = 128; s > 0; s >>= 1) {
        if (tid < s) red[tid] = fmaxf(red[tid], red[tid + s]);
        __syncthreads();
    }
    mx = red[0];
    __syncthreads();

    float sum = 0.f;
    #pragma unroll
    for (int i = 0; i < 4; i++) {
        v[i].x = __expf(v[i].x - mx);
        v[i].y = __expf(v[i].y - mx);
        sum += v[i].x + v[i].y;
    }
    red[tid] = sum; __syncthreads();
    for (int s = 128; s > 0; s >>= 1) {
        if (tid < s) red[tid] += red[tid + s];
        __syncthreads();
    }
    const float inv = 1.0f / red[0];
    #pragma unroll
    for (int i = 0; i < 4; i++)
        o[tid + i * 256] = packpair(v[i].x * inv, v[i].y * inv);
}

// ============================================================================
template <typename T>
static T* symaddr(const void* s) {
    void* p = nullptr;
    cudaGetSymbolAddress(&p, s);
    return (T*)p;
}

extern "C" void kernel_launch(void* const* d_in, const int* in_sizes, int n_in,
                              void* d_out, int out_size)
{
    const float* x    = (const float*)d_in[0];
    const float* cm   = (const float*)d_in[1];
    const float* am   = (const float*)d_in[2];
    const float* rq_w = (const float*)d_in[3];
    const float* rk_w = (const float*)d_in[4];
    const float* rv_w = (const float*)d_in[5];
    const float* ro_w = (const float*)d_in[6];
    const float* cq_w = (const float*)d_in[7];
    const float* ck_w = (const float*)d_in[8];
    const float* cv_w = (const float*)d_in[9];
    const float* co_w = (const float*)d_in[10];
    const float* rq_b = (const float*)d_in[11];
    const float* rk_b = (const float*)d_in[12];
    const float* rv_b = (const float*)d_in[13];
    const float* ro_b = (const float*)d_in[14];
    const float* cq_b = (const float*)d_in[15];
    const float* ck_b = (const float*)d_in[16];
    const float* cv_b = (const float*)d_in[17];
    const float* co_b = (const float*)d_in[18];
    const float* r_cb = (const float*)d_in[19];
    const float* c_cb = (const float*)d_in[20];
    const float* out_w = (const float*)d_in[21];
    const float* out_b = (const float*)d_in[22];
    float* out = (float*)d_out;

    uint2* xp    = symaddr<uint2>(g_xp);
    uint2* wqkvp = symaddr<uint2>(g_wqkvp);
    float* bqkv  = symaddr<float>(g_bqkv);
    uint2* qkvp  = symaddr<uint2>(g_qkvp);
    uint2* vf2   = symaddr<uint2>(g_vf2);
    float* sc    = symaddr<float>(g_sc);
    uint2* scp   = symaddr<uint2>(g_scp);
    uint2* catp2 = symaddr<uint2>(g_catp2);
    uint2* rowp  = symaddr<uint2>(g_rowp);
    uint2* cowp  = symaddr<uint2>(g_cowp);
    uint2* outwp = symaddr<uint2>(g_outwp);
    float* w1f   = symaddr<float>(g_w1f);
    float* w2f   = symaddr<float>(g_w2f);
    uint2* fwp   = symaddr<uint2>(g_fwp);
    float* biasf = symaddr<float>(g_biasf);

    static bool s_init = false;
    static cudaStream_t s2, s3;
    static cudaEvent_t evStart, evFork, evV, evJoin2, evJoin3;
    if (!s_init) {
        cudaStreamCreateWithFlags(&s2, cudaStreamNonBlocking);
        cudaStreamCreateWithFlags(&s3, cudaStreamNonBlocking);
        cudaEventCreateWithFlags(&evStart, cudaEventDisableTiming);
        cudaEventCreateWithFlags(&evFork, cudaEventDisableTiming);
        cudaEventCreateWithFlags(&evV, cudaEventDisableTiming);
        cudaEventCreateWithFlags(&evJoin2, cudaEventDisableTiming);
        cudaEventCreateWithFlags(&evJoin3, cudaEventDisableTiming);
        cudaFuncSetAttribute(flash_reg, cudaFuncAttributeMaxDynamicSharedMemorySize, FLASH_SMEM);
        cudaFuncSetAttribute(gemm_bf3_128, cudaFuncAttributeMaxDynamicSharedMemorySize, GEMM_SMEM);
        s_init = true;
    }

    dim3 blk(128);

    // ---- fork s3 FROM the capturing stream ----
    cudaEventRecord(evStart, 0);
    cudaStreamWaitEvent(s3, evStart, 0);

    // ---- s3: output-weight fusion ----
    {
        const int tot66 = 384 * 768;
        split_f1<<<(294912 + 255) / 256, 256, 0, s3>>>(ro_w, rowp, 294912);
        split_f1<<<(294912 + 255) / 256, 256, 0, s3>>>(co_w, cowp, 294912);
        pack_f2<<<(768 * 768 + 255) / 256, 256, 0, s3>>>(out_w, outwp, 768, 768, 0, 768 * 768);
        dim3 gw(768 / 128, 768 / 128, 1);
        gemm_bf3_128<<<gw, blk, GEMM_SMEM, s3>>>(rowp, outwp, w1f, nullptr, nullptr,
                                                 768, 384, 768, 768, 0,
                                                 0, 0, 0, 0, 0, 1);
        gemm_bf3_128<<<gw, blk, GEMM_SMEM, s3>>>(cowp, outwp + (size_t)384 * 768, w2f,
                                                 nullptr, nullptr,
                                                 768, 384, 768, 768, 0,
                                                 0, 0, 0, 0, 0, 1);
        pack_f2<<<(tot66 + 255) / 256, 256, 0, s3>>>(w1f, fwp, 768, 768, 0, tot66);
        pack_f2<<<(tot66 + 255) / 256, 256, 0, s3>>>(w2f, fwp + (size_t)384 * 768, 768, 768, 0, tot66);
        fuse_bias<<<3, 256, 0, s3>>>(ro_b, co_b, out_w, out_b, biasf);
        cudaEventRecord(evJoin3, s3);
    }

    // ---- main: QKV weight/bias/x packs ----
    {
        dim3 g6((384 * 768 + 255) / 256, 6);
        pack_w6<<<g6, 256>>>(rq_w, rk_w, rv_w, cq_w, ck_w, cv_w, wqkvp);
        fold_bias<<<(NQKV + 255) / 256, 256>>>(rq_b, rk_b, rv_b, cq_b, ck_b, cv_b,
                                               r_cb, c_cb, bqkv);
        const int tp = M_TOT * 384;
        split_f1<<<(tp + 255) / 256, 256>>>(x, xp, tp);
    }

    // ---- fused QKV projection ----
    dim3 gq(NQKV / 128, M_TOT / 128, 1);
    gemm_bf3_128<<<gq, blk, GEMM_SMEM>>>(xp, wqkvp, nullptr, qkvp, bqkv,
                                         E_DIM, 384, NQKV, 0, 2304,
                                         0, 0, 0, 0, 0, 1);

    // ---- fork: cultural scores+softmax need only qkvp ----
    cudaEventRecord(evFork, 0);
    cudaStreamWaitEvent(s2, evFork, 0);
    {
        const float scale_c = 1.0f / sqrtf((float)HD_C);
        dim3 gsc(S_LEN / 64, S_LEN / 128, B_SZ * NH_C);
        gemm_bf3_nt_scores<<<gsc, blk, 0, s2>>>(qkvp + 1152, qkvp + 1536, sc,
                                                am, cm, scale_c, HD_C, NH_C, 2304);
        softmax_pack<<<B_SZ * NH_C * S_LEN, 256, 0, s2>>>(sc, scp);
    }

    // ---- main: split V, then flash ----
    {
        const int tv = B_SZ * 1024 * 1536;
        split_v<<<(tv + 255) / 256, 256>>>(qkvp, vf2);
        cudaEventRecord(evV, 0);

        const float scale_r = 1.0f / sqrtf((float)HD_R);
        dim3 gf(16, B_SZ * NH_R);
        flash_reg<<<gf, 256, FLASH_SMEM>>>(qkvp, vf2, am, catp2, scale_r);
    }

    // ---- side: cultural PV writes att_cul into catp2 cols 384-767 ----
    {
        cudaStreamWaitEvent(s2, evV, 0);
        dim3 gac(HD_C / 128, S_LEN / 128, B_SZ * NH_C);
        gemm_bf3_128<<<gac, blk, GEMM_SMEM, s2>>>(scp, vf2 + 768, nullptr, catp2 + 384, nullptr,
                                                  S_LEN, 1024, 1536, 0, 768,
                                                  (long long)S_LEN * 1024,
                                                  (long long)1024 * 1536, HD_C,
                                                  (long long)S_LEN * 768, HD_C / 2, NH_C);
        cudaEventRecord(evJoin2, s2);
    }

    // ---- join both side streams ----
    cudaStreamWaitEvent(0, evJoin2, 0);
    cudaStreamWaitEvent(0, evJoin3, 0);

    // ---- fused final: out = [att_reg|att_cul] @ [W1;W2] + biasf ----
    dim3 gp(E_DIM / 128, M_TOT / 128, 1);
    gemm_bf3_128<<<gp, blk, GEMM_SMEM>>>(catp2, fwp, out, nullptr, biasf,
                                         2 * E_DIM, 768, 768, 768, 0,
                                         0, 0, 0, 0, 0, 1);
}